// round 1
// baseline (speedup 1.0000x reference)
#include <cuda_runtime.h>

#define B_ 4
#define T_ 4096
#define D_ 1024
#define H_ 16
#define DK_ 64
#define M_ (B_*T_)          // 16384 rows
#define K_ D_               // 1024
#define N_ D_               // 1024
#define EPS 1e-6f

#define NSPLIT 16
#define TSPLIT (T_/NSPLIT)  // 256

// ---------------- scratch (device globals; no allocations allowed) ----------
__device__ float g_q[M_*D_];
__device__ float g_k[M_*D_];
__device__ float g_v[M_*D_];
__device__ float g_attn[M_*D_];
__device__ float g_kvp[NSPLIT*B_*H_*DK_*DK_];   // split partials of kv
__device__ float g_ksump[NSPLIT*B_*H_*DK_];     // split partials of ksum
__device__ float g_kv[B_*H_*DK_*DK_];
__device__ float g_ksum[B_*H_*DK_];

// ---------------- activation -------------------------------------------------
template<int ACT>
__device__ __forceinline__ float actf(float v) {
    if (ACT == 1) {
        // phi(x) = elu(x) + 1 :  x>0 -> x+1 ; x<=0 -> exp(x)
        return v > 0.f ? v + 1.f : __expf(v);
    }
    return v;
}

// ---------------- fp32 GEMM:  C[m][n] = act( sum_k A[m][k]*W[n][k] + bias[n] )
// A: [M_, K_] row-major, W: [N_, K_] row-major ("NT" gemm).
// 128x128 block tile, BK=16, 256 threads, 8x8 per-thread tile.
#define BM 128
#define BN 128
#define BK 16
#define SLD 132   // smem row stride (floats); multiple of 4 for float4 alignment

template<int ACT>
__device__ __forceinline__ void gemm_body(const float* __restrict__ A,
                                          const float* __restrict__ W,
                                          const float* __restrict__ bias,
                                          float* __restrict__ C) {
    __shared__ float As[BK * SLD];
    __shared__ float Ws[BK * SLD];

    const int tid = threadIdx.x;
    const int m0  = blockIdx.y * BM;
    const int n0  = blockIdx.x * BN;
    const int tx  = tid & 15;
    const int ty  = tid >> 4;
    const int tx4 = tx * 4;
    const int ty4 = ty * 4;

    float acc[8][8];
#pragma unroll
    for (int i = 0; i < 8; i++)
#pragma unroll
        for (int j = 0; j < 8; j++) acc[i][j] = 0.f;

    const float* Ap = A + (size_t)m0 * K_;
    const float* Wp = W + (size_t)n0 * K_;

    for (int k0 = 0; k0 < K_; k0 += BK) {
        // ---- load tiles (each thread: 2x A-float4, 2x W-float4) ----
#pragma unroll
        for (int it = 0; it < 2; it++) {
            int idx = tid + it * 256;      // 0..511
            int row = idx >> 2;            // 0..127
            int c4  = (idx & 3) * 4;       // 0,4,8,12
            float4 av = *(const float4*)(Ap + (size_t)row * K_ + k0 + c4);
            float4 wv = *(const float4*)(Wp + (size_t)row * K_ + k0 + c4);
            As[(c4+0)*SLD + row] = av.x;
            As[(c4+1)*SLD + row] = av.y;
            As[(c4+2)*SLD + row] = av.z;
            As[(c4+3)*SLD + row] = av.w;
            Ws[(c4+0)*SLD + row] = wv.x;
            Ws[(c4+1)*SLD + row] = wv.y;
            Ws[(c4+2)*SLD + row] = wv.z;
            Ws[(c4+3)*SLD + row] = wv.w;
        }
        __syncthreads();

#pragma unroll
        for (int kk = 0; kk < BK; kk++) {
            float a[8], b[8];
            float4 t4;
            t4 = *(const float4*)&As[kk*SLD + ty4];        a[0]=t4.x; a[1]=t4.y; a[2]=t4.z; a[3]=t4.w;
            t4 = *(const float4*)&As[kk*SLD + 64 + ty4];   a[4]=t4.x; a[5]=t4.y; a[6]=t4.z; a[7]=t4.w;
            t4 = *(const float4*)&Ws[kk*SLD + tx4];        b[0]=t4.x; b[1]=t4.y; b[2]=t4.z; b[3]=t4.w;
            t4 = *(const float4*)&Ws[kk*SLD + 64 + tx4];   b[4]=t4.x; b[5]=t4.y; b[6]=t4.z; b[7]=t4.w;
#pragma unroll
            for (int i = 0; i < 8; i++)
#pragma unroll
                for (int j = 0; j < 8; j++)
                    acc[i][j] = fmaf(a[i], b[j], acc[i][j]);
        }
        __syncthreads();
    }

    // ---- epilogue: bias + activation + float4 stores ----
    float bvals[8];
#pragma unroll
    for (int j = 0; j < 4; j++) {
        bvals[j]     = bias[n0 + tx4 + j];
        bvals[j + 4] = bias[n0 + 64 + tx4 + j];
    }
#pragma unroll
    for (int ih = 0; ih < 2; ih++) {
#pragma unroll
        for (int ii = 0; ii < 4; ii++) {
            int i = ih * 4 + ii;
            int m = m0 + (ih ? 64 + ty4 : ty4) + ii;
#pragma unroll
            for (int jh = 0; jh < 2; jh++) {
                float4 o;
                o.x = actf<ACT>(acc[i][jh*4+0] + bvals[jh*4+0]);
                o.y = actf<ACT>(acc[i][jh*4+1] + bvals[jh*4+1]);
                o.z = actf<ACT>(acc[i][jh*4+2] + bvals[jh*4+2]);
                o.w = actf<ACT>(acc[i][jh*4+3] + bvals[jh*4+3]);
                *(float4*)&C[(size_t)m * N_ + n0 + (jh ? 64 + tx4 : tx4)] = o;
            }
        }
    }
}

__global__ __launch_bounds__(256) void gemm_q_kernel(const float* __restrict__ A,
                                                     const float* __restrict__ W,
                                                     const float* __restrict__ b) {
    gemm_body<1>(A, W, b, g_q);
}
__global__ __launch_bounds__(256) void gemm_k_kernel(const float* __restrict__ A,
                                                     const float* __restrict__ W,
                                                     const float* __restrict__ b) {
    gemm_body<1>(A, W, b, g_k);
}
__global__ __launch_bounds__(256) void gemm_v_kernel(const float* __restrict__ A,
                                                     const float* __restrict__ W,
                                                     const float* __restrict__ b) {
    gemm_body<0>(A, W, b, g_v);
}
__global__ __launch_bounds__(256) void gemm_o_kernel(const float* __restrict__ W,
                                                     const float* __restrict__ b,
                                                     float* __restrict__ out) {
    gemm_body<0>(g_attn, W, b, out);
}

// ---------------- kv summary: kv[b,h] = sum_t k_t (x) v_t ; ksum[b,h] = sum_t k_t
// grid (B*H, NSPLIT), 256 threads; deterministic split partials.
__global__ __launch_bounds__(256) void kv_kernel() {
    __shared__ float ks[8 * 64];
    __shared__ float vs[8 * 64];
    const int tid   = threadIdx.x;
    const int bh    = blockIdx.x;          // 0..63
    const int split = blockIdx.y;          // 0..NSPLIT-1
    const int b     = bh >> 4;
    const int h     = bh & 15;
    const int tbase = split * TSPLIT;

    const float* kb = g_k + ((size_t)(b * T_ + tbase) * D_) + h * DK_;
    const float* vb = g_v + ((size_t)(b * T_ + tbase) * D_) + h * DK_;

    const int r0 = (tid >> 4) * 4;   // row base in [0,64)
    const int c0 = (tid & 15) * 4;   // col base in [0,64)

    float acc[4][4];
#pragma unroll
    for (int i = 0; i < 4; i++)
#pragma unroll
        for (int j = 0; j < 4; j++) acc[i][j] = 0.f;
    float s = 0.f;

    for (int g = 0; g < TSPLIT / 8; g++) {
        __syncthreads();
        for (int i = tid; i < 512; i += 256) {
            int tt = i >> 6, d = i & 63;
            ks[i] = kb[(size_t)(g * 8 + tt) * D_ + d];
            vs[i] = vb[(size_t)(g * 8 + tt) * D_ + d];
        }
        __syncthreads();
#pragma unroll
        for (int tt = 0; tt < 8; tt++) {
            float4 k4 = *(float4*)&ks[tt * 64 + r0];
            float4 v4 = *(float4*)&vs[tt * 64 + c0];
            float kr[4] = {k4.x, k4.y, k4.z, k4.w};
            float vc[4] = {v4.x, v4.y, v4.z, v4.w};
#pragma unroll
            for (int i = 0; i < 4; i++)
#pragma unroll
                for (int j = 0; j < 4; j++)
                    acc[i][j] = fmaf(kr[i], vc[j], acc[i][j]);
        }
        if (tid < 64) {
#pragma unroll
            for (int tt = 0; tt < 8; tt++) s += ks[tt * 64 + tid];
        }
    }

    float* dst = g_kvp + (size_t)split * (B_*H_*DK_*DK_) + (size_t)bh * (DK_*DK_);
#pragma unroll
    for (int i = 0; i < 4; i++)
#pragma unroll
        for (int j = 0; j < 4; j++)
            dst[(r0 + i) * DK_ + c0 + j] = acc[i][j];
    if (tid < 64)
        g_ksump[(size_t)split * (B_*H_*DK_) + bh * DK_ + tid] = s;
}

// fixed-order reduction of split partials (deterministic)
__global__ __launch_bounds__(256) void kv_reduce_kernel() {
    int i = blockIdx.x * 256 + threadIdx.x;
    if (i < B_*H_*DK_*DK_) {
        float s = 0.f;
#pragma unroll
        for (int sp = 0; sp < NSPLIT; sp++) s += g_kvp[(size_t)sp * (B_*H_*DK_*DK_) + i];
        g_kv[i] = s;
    }
    if (i < B_*H_*DK_) {
        float s = 0.f;
#pragma unroll
        for (int sp = 0; sp < NSPLIT; sp++) s += g_ksump[(size_t)sp * (B_*H_*DK_) + i];
        g_ksum[i] = s;
    }
}

// ---------------- attention apply: out[t,:] = z_t * (q_t @ kv)
// grid (B*H, T/64), 256 threads; 64 t-rows per block.
__global__ __launch_bounds__(256) void attn_kernel() {
    __shared__ float qs[64 * 64];    // [d][t]
    __shared__ float kvs[64 * 64];   // [d][m]
    __shared__ float ksums[64];
    __shared__ float zs[64];

    const int tid = threadIdx.x;
    const int bh  = blockIdx.x;
    const int b   = bh >> 4;
    const int h   = bh & 15;
    const int t0  = blockIdx.y * 64;

    const float* qbase = g_q + ((size_t)(b * T_ + t0) * D_) + h * DK_;

    for (int i = tid; i < 4096; i += 256)
        kvs[i] = g_kv[(size_t)bh * 4096 + i];
    if (tid < 64)
        ksums[tid] = g_ksum[bh * DK_ + tid] + EPS;

    // load q tile [64 t][64 d] transposed -> qs[d][t]
    for (int i = tid; i < 1024; i += 256) {
        int t  = i >> 4;
        int c4 = (i & 15) * 4;
        float4 v = *(const float4*)(qbase + (size_t)t * D_ + c4);
        qs[(c4+0)*64 + t] = v.x;
        qs[(c4+1)*64 + t] = v.y;
        qs[(c4+2)*64 + t] = v.z;
        qs[(c4+3)*64 + t] = v.w;
    }
    __syncthreads();

    if (tid < 64) {
        float zn = 0.f;
#pragma unroll
        for (int d = 0; d < 64; d++) zn = fmaf(qs[d*64 + tid], ksums[d], zn);
        zs[tid] = 1.f / (zn + EPS);
    }
    __syncthreads();

    const int tx = tid & 15;   // m dim (4 cols each)
    const int ty = tid >> 4;   // t dim (4 rows each)
    float acc[4][4];
#pragma unroll
    for (int i = 0; i < 4; i++)
#pragma unroll
        for (int j = 0; j < 4; j++) acc[i][j] = 0.f;

#pragma unroll
    for (int d = 0; d < 64; d++) {
        float4 a4 = *(float4*)&qs[d*64 + ty*4];
        float4 b4 = *(float4*)&kvs[d*64 + tx*4];
        float a[4] = {a4.x, a4.y, a4.z, a4.w};
        float bb[4] = {b4.x, b4.y, b4.z, b4.w};
#pragma unroll
        for (int i = 0; i < 4; i++)
#pragma unroll
            for (int j = 0; j < 4; j++)
                acc[i][j] = fmaf(a[i], bb[j], acc[i][j]);
    }

#pragma unroll
    for (int i = 0; i < 4; i++) {
        int t = ty * 4 + i;
        float z = zs[t];
        float4 o = make_float4(acc[i][0]*z, acc[i][1]*z, acc[i][2]*z, acc[i][3]*z);
        *(float4*)&g_attn[(size_t)(b * T_ + t0 + t) * D_ + h * DK_ + tx * 4] = o;
    }
}

// ---------------- launch ----------------------------------------------------
extern "C" void kernel_launch(void* const* d_in, const int* in_sizes, int n_in,
                              void* d_out, int out_size) {
    const float* x  = (const float*)d_in[0];
    const float* Wq = (const float*)d_in[1];
    const float* bq = (const float*)d_in[2];
    const float* Wk = (const float*)d_in[3];
    const float* bk = (const float*)d_in[4];
    const float* Wv = (const float*)d_in[5];
    const float* bv = (const float*)d_in[6];
    const float* Wo = (const float*)d_in[7];
    const float* bo = (const float*)d_in[8];
    float* out = (float*)d_out;

    dim3 gg(N_ / BN, M_ / BM);   // (8, 128)
    gemm_q_kernel<<<gg, 256>>>(x, Wq, bq);
    gemm_k_kernel<<<gg, 256>>>(x, Wk, bk);
    gemm_v_kernel<<<gg, 256>>>(x, Wv, bv);
    kv_kernel<<<dim3(B_*H_, NSPLIT), 256>>>();
    kv_reduce_kernel<<<(B_*H_*DK_*DK_ + 255) / 256, 256>>>();
    attn_kernel<<<dim3(B_*H_, T_ / 64), 256>>>();
    gemm_o_kernel<<<gg, 256>>>(Wo, bo, out);
}

// round 4
// speedup vs baseline: 2.2335x; 2.2335x over previous
#include <cuda_runtime.h>
#include <cuda_bf16.h>
#include <cstdint>

#define B_ 4
#define T_ 4096
#define D_ 1024
#define H_ 16
#define DK_ 64
#define M_ (B_*T_)          // 16384
#define K_ D_               // 1024
#define N_ D_               // 1024
#define EPS 1e-6f

#define NSPLIT 64
#define TSPLIT (T_/NSPLIT)  // 64

// ---------------- scratch (device globals; no allocations allowed) ----------
__device__ float g_q[M_*D_];
__device__ float g_k[M_*D_];
__device__ float g_v[M_*D_];
__device__ float g_attn[M_*D_];
__device__ float g_kvp[NSPLIT*B_*H_*DK_*DK_];
__device__ float g_ksump[NSPLIT*B_*H_*DK_];
__device__ float g_kv[B_*H_*DK_*DK_];
__device__ float g_ksum[B_*H_*DK_];

// ---------------- helpers -----------------------------------------------------
__device__ __forceinline__ uint32_t smem_u32(const void* p) {
    uint32_t a;
    asm("{ .reg .u64 t; cvta.to.shared.u64 t, %1; cvt.u32.u64 %0, t; }" : "=r"(a) : "l"(p));
    return a;
}

#define LDSM_X4(r, addr) \
    asm volatile("ldmatrix.sync.aligned.m8n8.x4.shared.b16 {%0,%1,%2,%3}, [%4];" \
        : "=r"((r)[0]), "=r"((r)[1]), "=r"((r)[2]), "=r"((r)[3]) : "r"(addr))

// NON-trans x2: W stored [n][k] row-major already matches the .col B fragment
// (lane l needs two k-consecutive bf16 of row n=l/4 -> plain ldmatrix fragment).
#define LDSM_X2(r, addr) \
    asm volatile("ldmatrix.sync.aligned.m8n8.x2.shared.b16 {%0,%1}, [%2];" \
        : "=r"((r)[0]), "=r"((r)[1]) : "r"(addr))

#define MMA_BF16(d, a, b) \
    asm volatile("mma.sync.aligned.m16n8k16.row.col.f32.bf16.bf16.f32 " \
        "{%0,%1,%2,%3},{%4,%5,%6,%7},{%8,%9},{%0,%1,%2,%3};" \
        : "+f"((d)[0]), "+f"((d)[1]), "+f"((d)[2]), "+f"((d)[3]) \
        : "r"((a)[0]), "r"((a)[1]), "r"((a)[2]), "r"((a)[3]), \
          "r"((b)[0]), "r"((b)[1]))

template<int ACT>
__device__ __forceinline__ float actf(float v) {
    if (ACT == 1) return v > 0.f ? v + 1.f : __expf(v);   // elu(x)+1
    return v;
}

// split fp32 -> (hi, lo) bf16 pairs
__device__ __forceinline__ void cvt_split(float4 f, uint2& hi, uint2& lo) {
    uint32_t hp0, hp1, lp0, lp1;
    asm("cvt.rn.bf16x2.f32 %0, %1, %2;" : "=r"(hp0) : "f"(f.y), "f"(f.x));
    asm("cvt.rn.bf16x2.f32 %0, %1, %2;" : "=r"(hp1) : "f"(f.w), "f"(f.z));
    float l0 = f.x - __uint_as_float(hp0 << 16);
    float l1 = f.y - __uint_as_float(hp0 & 0xffff0000u);
    float l2 = f.z - __uint_as_float(hp1 << 16);
    float l3 = f.w - __uint_as_float(hp1 & 0xffff0000u);
    asm("cvt.rn.bf16x2.f32 %0, %1, %2;" : "=r"(lp0) : "f"(l1), "f"(l0));
    asm("cvt.rn.bf16x2.f32 %0, %1, %2;" : "=r"(lp1) : "f"(l3), "f"(l2));
    hi.x = hp0; hi.y = hp1;
    lo.x = lp0; lo.y = lp1;
}

// ---------------- HMMA GEMM: C = act(A @ W^T + bias) --------------------------
// A:[M_,K_], W:[N_,K_] fp32. bf16 hi/lo split, 3 MMA products, fp32 reg accum.
// CTA tile 128x128, 8 warps (2x4), warp tile 64x32, BK=32 floats.
#define BKF 32
#define NCHUNK (K_/BKF)      // 32
#define PADB 80              // bytes per smem row (40 bf16) - conflict-free ldmatrix
#define TILE_B (128*PADB)    // 10240
#define STAGE_B (4*TILE_B)   // Ahi, Alo, Whi, Wlo = 40960
#define GSMEM (2*STAGE_B)    // 81920

__device__ __forceinline__ void load_g(const float* __restrict__ A,
                                       const float* __restrict__ W,
                                       int m0, int n0, int kc, int tid,
                                       float4* sa, float4* sw) {
#pragma unroll
    for (int j = 0; j < 4; j++) {
        int idx = tid + j * 256;
        int r   = idx >> 3;
        int c4  = (idx & 7) << 2;
        sa[j] = *(const float4*)(A + (size_t)(m0 + r) * K_ + kc * BKF + c4);
        sw[j] = *(const float4*)(W + (size_t)(n0 + r) * K_ + kc * BKF + c4);
    }
}

__device__ __forceinline__ void store_s(char* base, int tid,
                                        const float4* sa, const float4* sw) {
#pragma unroll
    for (int j = 0; j < 4; j++) {
        int idx = tid + j * 256;
        int r   = idx >> 3;
        int c4  = (idx & 7) << 2;
        int off = r * PADB + (c4 << 1);
        uint2 hi, lo;
        cvt_split(sa[j], hi, lo);
        *(uint2*)(base + off)          = hi;
        *(uint2*)(base + TILE_B + off) = lo;
        cvt_split(sw[j], hi, lo);
        *(uint2*)(base + 2*TILE_B + off) = hi;
        *(uint2*)(base + 3*TILE_B + off) = lo;
    }
}

template<int ACT>
__device__ __forceinline__ void gemm_body(const float* __restrict__ A,
                                          const float* __restrict__ W,
                                          const float* __restrict__ bias,
                                          float* __restrict__ C) {
    extern __shared__ char smem[];
    const int tid    = threadIdx.x;
    const int lane   = tid & 31;
    const int wid    = tid >> 5;
    const int warp_m = wid >> 2;       // 0..1
    const int warp_n = wid & 3;        // 0..3
    const int m0     = blockIdx.y * 128;
    const int n0     = blockIdx.x * 128;
    const uint32_t sbase = smem_u32(smem);

    float acc[4][4][4];
#pragma unroll
    for (int mi = 0; mi < 4; mi++)
#pragma unroll
        for (int ni = 0; ni < 4; ni++)
#pragma unroll
            for (int t = 0; t < 4; t++) acc[mi][ni][t] = 0.f;

    float4 sa[4], sw4[4];
    load_g(A, W, m0, n0, 0, tid, sa, sw4);
    store_s(smem, tid, sa, sw4);
    __syncthreads();

    int p = 0;
    for (int kc = 0; kc < NCHUNK; kc++) {
        const bool pre = (kc + 1) < NCHUNK;
        if (pre) load_g(A, W, m0, n0, kc + 1, tid, sa, sw4);

        const uint32_t base = sbase + p * STAGE_B;

#pragma unroll
        for (int ks = 0; ks < 2; ks++) {
            // ---- B fragments (hi, lo) for all 4 n-tiles ----
            uint32_t bhi[4][2], blo[4][2];
            const int l2   = lane & 15;
            const int bk   = ks * 32 + ((l2 >> 3) & 1) * 16;
            const int brow = warp_n * 32 + (l2 & 7);
#pragma unroll
            for (int ni = 0; ni < 4; ni++) {
                uint32_t addr = base + 2*TILE_B + (uint32_t)(brow + ni * 8) * PADB + bk;
                LDSM_X2(bhi[ni], addr);
                LDSM_X2(blo[ni], addr + TILE_B);
            }
            // ---- A fragments per m-tile, 3-product MMA ----
            const int arow = warp_m * 64 + (lane & 15);
            const int ak   = ks * 32 + (lane >> 4) * 16;
#pragma unroll
            for (int mi = 0; mi < 4; mi++) {
                uint32_t aaddr = base + (uint32_t)(arow + mi * 16) * PADB + ak;
                uint32_t ah[4], al[4];
                LDSM_X4(ah, aaddr);
                LDSM_X4(al, aaddr + TILE_B);
#pragma unroll
                for (int ni = 0; ni < 4; ni++) {
                    MMA_BF16(acc[mi][ni], ah, bhi[ni]);
                    MMA_BF16(acc[mi][ni], ah, blo[ni]);
                    MMA_BF16(acc[mi][ni], al, bhi[ni]);
                }
            }
        }

        if (pre) store_s(smem + (p ^ 1) * STAGE_B, tid, sa, sw4);
        __syncthreads();
        p ^= 1;
    }

    // ---- epilogue: bias + activation ----
#pragma unroll
    for (int mi = 0; mi < 4; mi++) {
        int r0 = m0 + warp_m * 64 + mi * 16 + (lane >> 2);
#pragma unroll
        for (int ni = 0; ni < 4; ni++) {
            int c = n0 + warp_n * 32 + ni * 8 + (lane & 3) * 2;
            float b0v = bias[c], b1v = bias[c + 1];
            float2 o0, o1;
            o0.x = actf<ACT>(acc[mi][ni][0] + b0v);
            o0.y = actf<ACT>(acc[mi][ni][1] + b1v);
            o1.x = actf<ACT>(acc[mi][ni][2] + b0v);
            o1.y = actf<ACT>(acc[mi][ni][3] + b1v);
            *(float2*)&C[(size_t)r0 * N_ + c]       = o0;
            *(float2*)&C[(size_t)(r0 + 8) * N_ + c] = o1;
        }
    }
}

__global__ void __launch_bounds__(256, 1)
gemm_q_tc(const float* __restrict__ A, const float* __restrict__ W, const float* __restrict__ b) {
    gemm_body<1>(A, W, b, g_q);
}
__global__ void __launch_bounds__(256, 1)
gemm_k_tc(const float* __restrict__ A, const float* __restrict__ W, const float* __restrict__ b) {
    gemm_body<1>(A, W, b, g_k);
}
__global__ void __launch_bounds__(256, 1)
gemm_v_tc(const float* __restrict__ A, const float* __restrict__ W, const float* __restrict__ b) {
    gemm_body<0>(A, W, b, g_v);
}
__global__ void __launch_bounds__(256, 1)
gemm_o_tc(const float* __restrict__ W, const float* __restrict__ b, float* __restrict__ out) {
    gemm_body<0>(g_attn, W, b, out);
}

// ---------------- kv summary (split partials, deterministic) ------------------
__global__ __launch_bounds__(256) void kv_kernel() {
    __shared__ float ks[8 * 64];
    __shared__ float vs[8 * 64];
    const int tid   = threadIdx.x;
    const int bh    = blockIdx.x;
    const int split = blockIdx.y;
    const int b     = bh >> 4;
    const int h     = bh & 15;
    const int tbase = split * TSPLIT;

    const float* kb = g_k + ((size_t)(b * T_ + tbase) * D_) + h * DK_;
    const float* vb = g_v + ((size_t)(b * T_ + tbase) * D_) + h * DK_;

    const int r0 = (tid >> 4) * 4;
    const int c0 = (tid & 15) * 4;

    float acc[4][4];
#pragma unroll
    for (int i = 0; i < 4; i++)
#pragma unroll
        for (int j = 0; j < 4; j++) acc[i][j] = 0.f;
    float s = 0.f;

    for (int g = 0; g < TSPLIT / 8; g++) {
        __syncthreads();
        for (int i = tid; i < 512; i += 256) {
            int tt = i >> 6, d = i & 63;
            ks[i] = kb[(size_t)(g * 8 + tt) * D_ + d];
            vs[i] = vb[(size_t)(g * 8 + tt) * D_ + d];
        }
        __syncthreads();
#pragma unroll
        for (int tt = 0; tt < 8; tt++) {
            float4 k4 = *(float4*)&ks[tt * 64 + r0];
            float4 v4 = *(float4*)&vs[tt * 64 + c0];
            float kr[4] = {k4.x, k4.y, k4.z, k4.w};
            float vc[4] = {v4.x, v4.y, v4.z, v4.w};
#pragma unroll
            for (int i = 0; i < 4; i++)
#pragma unroll
                for (int j = 0; j < 4; j++)
                    acc[i][j] = fmaf(kr[i], vc[j], acc[i][j]);
        }
        if (tid < 64) {
#pragma unroll
            for (int tt = 0; tt < 8; tt++) s += ks[tt * 64 + tid];
        }
    }

    float* dst = g_kvp + (size_t)split * (B_*H_*DK_*DK_) + (size_t)bh * (DK_*DK_);
#pragma unroll
    for (int i = 0; i < 4; i++)
#pragma unroll
        for (int j = 0; j < 4; j++)
            dst[(r0 + i) * DK_ + c0 + j] = acc[i][j];
    if (tid < 64)
        g_ksump[(size_t)split * (B_*H_*DK_) + bh * DK_ + tid] = s;
}

__global__ __launch_bounds__(256) void kv_reduce_kernel() {
    int i = blockIdx.x * 256 + threadIdx.x;
    if (i < B_*H_*DK_*DK_) {
        float s = 0.f;
#pragma unroll
        for (int sp = 0; sp < NSPLIT; sp++) s += g_kvp[(size_t)sp * (B_*H_*DK_*DK_) + i];
        g_kv[i] = s;
    }
    if (i < B_*H_*DK_) {
        float s = 0.f;
#pragma unroll
        for (int sp = 0; sp < NSPLIT; sp++) s += g_ksump[(size_t)sp * (B_*H_*DK_) + i];
        g_ksum[i] = s;
    }
}

// ---------------- attention apply ---------------------------------------------
__global__ __launch_bounds__(256) void attn_kernel() {
    __shared__ float qs[64 * 64];
    __shared__ float kvs[64 * 64];
    __shared__ float ksums[64];
    __shared__ float zs[64];

    const int tid = threadIdx.x;
    const int bh  = blockIdx.x;
    const int b   = bh >> 4;
    const int h   = bh & 15;
    const int t0  = blockIdx.y * 64;

    const float* qbase = g_q + ((size_t)(b * T_ + t0) * D_) + h * DK_;

    for (int i = tid; i < 4096; i += 256)
        kvs[i] = g_kv[(size_t)bh * 4096 + i];
    if (tid < 64)
        ksums[tid] = g_ksum[bh * DK_ + tid] + EPS;

    for (int i = tid; i < 1024; i += 256) {
        int t  = i >> 4;
        int c4 = (i & 15) * 4;
        float4 v = *(const float4*)(qbase + (size_t)t * D_ + c4);
        qs[(c4+0)*64 + t] = v.x;
        qs[(c4+1)*64 + t] = v.y;
        qs[(c4+2)*64 + t] = v.z;
        qs[(c4+3)*64 + t] = v.w;
    }
    __syncthreads();

    if (tid < 64) {
        float zn = 0.f;
#pragma unroll
        for (int d = 0; d < 64; d++) zn = fmaf(qs[d*64 + tid], ksums[d], zn);
        zs[tid] = 1.f / (zn + EPS);
    }
    __syncthreads();

    const int tx = tid & 15;
    const int ty = tid >> 4;
    float acc[4][4];
#pragma unroll
    for (int i = 0; i < 4; i++)
#pragma unroll
        for (int j = 0; j < 4; j++) acc[i][j] = 0.f;

#pragma unroll
    for (int d = 0; d < 64; d++) {
        float4 a4 = *(float4*)&qs[d*64 + ty*4];
        float4 b4 = *(float4*)&kvs[d*64 + tx*4];
        float a[4] = {a4.x, a4.y, a4.z, a4.w};
        float bb[4] = {b4.x, b4.y, b4.z, b4.w};
#pragma unroll
        for (int i = 0; i < 4; i++)
#pragma unroll
            for (int j = 0; j < 4; j++)
                acc[i][j] = fmaf(a[i], bb[j], acc[i][j]);
    }

#pragma unroll
    for (int i = 0; i < 4; i++) {
        int t = ty * 4 + i;
        float z = zs[t];
        float4 o = make_float4(acc[i][0]*z, acc[i][1]*z, acc[i][2]*z, acc[i][3]*z);
        *(float4*)&g_attn[(size_t)(b * T_ + t0 + t) * D_ + h * DK_ + tx * 4] = o;
    }
}

// ---------------- launch ----------------------------------------------------
extern "C" void kernel_launch(void* const* d_in, const int* in_sizes, int n_in,
                              void* d_out, int out_size) {
    const float* x  = (const float*)d_in[0];
    const float* Wq = (const float*)d_in[1];
    const float* bq = (const float*)d_in[2];
    const float* Wk = (const float*)d_in[3];
    const float* bk = (const float*)d_in[4];
    const float* Wv = (const float*)d_in[5];
    const float* bv = (const float*)d_in[6];
    const float* Wo = (const float*)d_in[7];
    const float* bo = (const float*)d_in[8];
    float* out = (float*)d_out;

    static bool attr_set = false;
    if (!attr_set) {
        cudaFuncSetAttribute(gemm_q_tc, cudaFuncAttributeMaxDynamicSharedMemorySize, GSMEM);
        cudaFuncSetAttribute(gemm_k_tc, cudaFuncAttributeMaxDynamicSharedMemorySize, GSMEM);
        cudaFuncSetAttribute(gemm_v_tc, cudaFuncAttributeMaxDynamicSharedMemorySize, GSMEM);
        cudaFuncSetAttribute(gemm_o_tc, cudaFuncAttributeMaxDynamicSharedMemorySize, GSMEM);
        attr_set = true;
    }

    dim3 gg(N_ / 128, M_ / 128);   // (8, 128)
    gemm_q_tc<<<gg, 256, GSMEM>>>(x, Wq, bq);
    gemm_k_tc<<<gg, 256, GSMEM>>>(x, Wk, bk);
    gemm_v_tc<<<gg, 256, GSMEM>>>(x, Wv, bv);
    kv_kernel<<<dim3(B_*H_, NSPLIT), 256>>>();
    kv_reduce_kernel<<<(B_*H_*DK_*DK_ + 255) / 256, 256>>>();
    attn_kernel<<<dim3(B_*H_, T_ / 64), 256>>>();
    gemm_o_tc<<<gg, 256, GSMEM>>>(Wo, bo, out);
}

// round 5
// speedup vs baseline: 2.2768x; 1.0194x over previous
#include <cuda_runtime.h>
#include <cuda_bf16.h>
#include <cstdint>

#define B_ 4
#define T_ 4096
#define D_ 1024
#define H_ 16
#define DK_ 64
#define M_ (B_*T_)          // 16384
#define K_ D_               // 1024
#define N_ D_               // 1024
#define EPS 1e-6f

#define NSPLIT 64
#define TSPLIT (T_/NSPLIT)  // 64

// ---------------- scratch (device globals; no allocations allowed) ----------
__device__ float g_q[M_*D_];
__device__ float g_k[M_*D_];
__device__ float g_v[M_*D_];
__device__ float g_attn[M_*D_];
__device__ float g_kvp[NSPLIT*B_*H_*DK_*DK_];
__device__ float g_ksump[NSPLIT*B_*H_*DK_];
__device__ float g_kv[B_*H_*DK_*DK_];
__device__ float g_ksum[B_*H_*DK_];

// ---------------- helpers -----------------------------------------------------
__device__ __forceinline__ uint32_t smem_u32(const void* p) {
    uint32_t a;
    asm("{ .reg .u64 t; cvta.to.shared.u64 t, %1; cvt.u32.u64 %0, t; }" : "=r"(a) : "l"(p));
    return a;
}

#define LDSM_X4(r, addr) \
    asm volatile("ldmatrix.sync.aligned.m8n8.x4.shared.b16 {%0,%1,%2,%3}, [%4];" \
        : "=r"((r)[0]), "=r"((r)[1]), "=r"((r)[2]), "=r"((r)[3]) : "r"(addr))

#define LDSM_X2(r, addr) \
    asm volatile("ldmatrix.sync.aligned.m8n8.x2.shared.b16 {%0,%1}, [%2];" \
        : "=r"((r)[0]), "=r"((r)[1]) : "r"(addr))

#define MMA_BF16(d, a, b) \
    asm volatile("mma.sync.aligned.m16n8k16.row.col.f32.bf16.bf16.f32 " \
        "{%0,%1,%2,%3},{%4,%5,%6,%7},{%8,%9},{%0,%1,%2,%3};" \
        : "+f"((d)[0]), "+f"((d)[1]), "+f"((d)[2]), "+f"((d)[3]) \
        : "r"((a)[0]), "r"((a)[1]), "r"((a)[2]), "r"((a)[3]), \
          "r"((b)[0]), "r"((b)[1]))

template<int ACT>
__device__ __forceinline__ float actf(float v) {
    if (ACT == 1) return v > 0.f ? v + 1.f : __expf(v);   // elu(x)+1
    return v;
}

// split fp32 -> (hi, lo) bf16 pairs
__device__ __forceinline__ void cvt_split(float4 f, uint2& hi, uint2& lo) {
    uint32_t hp0, hp1, lp0, lp1;
    asm("cvt.rn.bf16x2.f32 %0, %1, %2;" : "=r"(hp0) : "f"(f.y), "f"(f.x));
    asm("cvt.rn.bf16x2.f32 %0, %1, %2;" : "=r"(hp1) : "f"(f.w), "f"(f.z));
    float l0 = f.x - __uint_as_float(hp0 << 16);
    float l1 = f.y - __uint_as_float(hp0 & 0xffff0000u);
    float l2 = f.z - __uint_as_float(hp1 << 16);
    float l3 = f.w - __uint_as_float(hp1 & 0xffff0000u);
    asm("cvt.rn.bf16x2.f32 %0, %1, %2;" : "=r"(lp0) : "f"(l1), "f"(l0));
    asm("cvt.rn.bf16x2.f32 %0, %1, %2;" : "=r"(lp1) : "f"(l3), "f"(l2));
    hi.x = hp0; hi.y = hp1;
    lo.x = lp0; lo.y = lp1;
}

// ---------------- HMMA GEMM: C = act(A @ W^T + bias) --------------------------
// A:[M_,K_], W:[N_,K_] fp32. bf16 hi/lo split, 3 MMA products, fp32 reg accum.
// CTA tile 128x128, 8 warps (2x4), warp tile 64x32, BK=32 floats.
#define BKF 32
#define NCHUNK (K_/BKF)      // 32
#define PADB 80              // bytes per smem row (40 bf16) - conflict-free ldmatrix
#define TILE_B (128*PADB)    // 10240
#define STAGE_B (4*TILE_B)   // Ahi, Alo, Whi, Wlo = 40960
#define GSMEM (2*STAGE_B)    // 81920

__device__ __forceinline__ void load_g(const float* __restrict__ A,
                                       const float* __restrict__ W,
                                       int m0, int n0, int kc, int tid,
                                       float4* sa, float4* sw) {
#pragma unroll
    for (int j = 0; j < 4; j++) {
        int idx = tid + j * 256;
        int r   = idx >> 3;
        int c4  = (idx & 7) << 2;
        sa[j] = *(const float4*)(A + (size_t)(m0 + r) * K_ + kc * BKF + c4);
        sw[j] = *(const float4*)(W + (size_t)(n0 + r) * K_ + kc * BKF + c4);
    }
}

__device__ __forceinline__ void store_s(char* base, int tid,
                                        const float4* sa, const float4* sw) {
#pragma unroll
    for (int j = 0; j < 4; j++) {
        int idx = tid + j * 256;
        int r   = idx >> 3;
        int c4  = (idx & 7) << 2;
        int off = r * PADB + (c4 << 1);
        uint2 hi, lo;
        cvt_split(sa[j], hi, lo);
        *(uint2*)(base + off)          = hi;
        *(uint2*)(base + TILE_B + off) = lo;
        cvt_split(sw[j], hi, lo);
        *(uint2*)(base + 2*TILE_B + off) = hi;
        *(uint2*)(base + 3*TILE_B + off) = lo;
    }
}

template<int ACT>
__device__ __forceinline__ void gemm_body(const float* __restrict__ A,
                                          const float* __restrict__ W,
                                          const float* __restrict__ bias,
                                          float* __restrict__ C) {
    extern __shared__ char smem[];
    const int tid    = threadIdx.x;
    const int lane   = tid & 31;
    const int wid    = tid >> 5;
    const int warp_m = wid >> 2;       // 0..1
    const int warp_n = wid & 3;        // 0..3
    const int m0     = blockIdx.y * 128;
    const int n0     = blockIdx.x * 128;
    const uint32_t sbase = smem_u32(smem);

    float acc[4][4][4];
#pragma unroll
    for (int mi = 0; mi < 4; mi++)
#pragma unroll
        for (int ni = 0; ni < 4; ni++)
#pragma unroll
            for (int t = 0; t < 4; t++) acc[mi][ni][t] = 0.f;

    float4 sa[4], sw4[4];
    load_g(A, W, m0, n0, 0, tid, sa, sw4);
    store_s(smem, tid, sa, sw4);
    __syncthreads();

    int p = 0;
    for (int kc = 0; kc < NCHUNK; kc++) {
        const bool pre = (kc + 1) < NCHUNK;
        if (pre) load_g(A, W, m0, n0, kc + 1, tid, sa, sw4);

        const uint32_t base = sbase + p * STAGE_B;

#pragma unroll
        for (int ks = 0; ks < 2; ks++) {
            // ---- B fragments (hi, lo) for all 4 n-tiles ----
            uint32_t bhi[4][2], blo[4][2];
            const int l2   = lane & 15;
            const int bk   = ks * 32 + ((l2 >> 3) & 1) * 16;
            const int brow = warp_n * 32 + (l2 & 7);
#pragma unroll
            for (int ni = 0; ni < 4; ni++) {
                uint32_t addr = base + 2*TILE_B + (uint32_t)(brow + ni * 8) * PADB + bk;
                LDSM_X2(bhi[ni], addr);
                LDSM_X2(blo[ni], addr + TILE_B);
            }
            // ---- ALL A fragments for this k-step ----
            const int arow = warp_m * 64 + (lane & 15);
            const int ak   = ks * 32 + (lane >> 4) * 16;
            uint32_t ah[4][4], al[4][4];
#pragma unroll
            for (int mi = 0; mi < 4; mi++) {
                uint32_t aaddr = base + (uint32_t)(arow + mi * 16) * PADB + ak;
                LDSM_X4(ah[mi], aaddr);
                LDSM_X4(al[mi], aaddr + TILE_B);
            }
            // ---- product-outermost MMA order: 16 independent accs between
            //      revisits of the same accumulator (hides HMMA latency) ----
#pragma unroll
            for (int mi = 0; mi < 4; mi++)
#pragma unroll
                for (int ni = 0; ni < 4; ni++)
                    MMA_BF16(acc[mi][ni], ah[mi], bhi[ni]);
#pragma unroll
            for (int mi = 0; mi < 4; mi++)
#pragma unroll
                for (int ni = 0; ni < 4; ni++)
                    MMA_BF16(acc[mi][ni], ah[mi], blo[ni]);
#pragma unroll
            for (int mi = 0; mi < 4; mi++)
#pragma unroll
                for (int ni = 0; ni < 4; ni++)
                    MMA_BF16(acc[mi][ni], al[mi], bhi[ni]);
        }

        if (pre) store_s(smem + (p ^ 1) * STAGE_B, tid, sa, sw4);
        __syncthreads();
        p ^= 1;
    }

    // ---- epilogue: bias + activation ----
#pragma unroll
    for (int mi = 0; mi < 4; mi++) {
        int r0 = m0 + warp_m * 64 + mi * 16 + (lane >> 2);
#pragma unroll
        for (int ni = 0; ni < 4; ni++) {
            int c = n0 + warp_n * 32 + ni * 8 + (lane & 3) * 2;
            float b0v = bias[c], b1v = bias[c + 1];
            float2 o0, o1;
            o0.x = actf<ACT>(acc[mi][ni][0] + b0v);
            o0.y = actf<ACT>(acc[mi][ni][1] + b1v);
            o1.x = actf<ACT>(acc[mi][ni][2] + b0v);
            o1.y = actf<ACT>(acc[mi][ni][3] + b1v);
            *(float2*)&C[(size_t)r0 * N_ + c]       = o0;
            *(float2*)&C[(size_t)(r0 + 8) * N_ + c] = o1;
        }
    }
}

__global__ void __launch_bounds__(256, 1)
gemm_q_tc(const float* __restrict__ A, const float* __restrict__ W, const float* __restrict__ b) {
    gemm_body<1>(A, W, b, g_q);
}
__global__ void __launch_bounds__(256, 1)
gemm_k_tc(const float* __restrict__ A, const float* __restrict__ W, const float* __restrict__ b) {
    gemm_body<1>(A, W, b, g_k);
}
__global__ void __launch_bounds__(256, 1)
gemm_v_tc(const float* __restrict__ A, const float* __restrict__ W, const float* __restrict__ b) {
    gemm_body<0>(A, W, b, g_v);
}
__global__ void __launch_bounds__(256, 1)
gemm_o_tc(const float* __restrict__ W, const float* __restrict__ b, float* __restrict__ out) {
    gemm_body<0>(g_attn, W, b, out);
}

// ---------------- kv summary (split partials, deterministic) ------------------
// 16 t-rows per smem stage: fewer barriers, more load MLP than 8-row version.
__global__ __launch_bounds__(256) void kv_kernel() {
    __shared__ float ks[16 * 64];
    __shared__ float vs[16 * 64];
    const int tid   = threadIdx.x;
    const int bh    = blockIdx.x;
    const int split = blockIdx.y;
    const int b     = bh >> 4;
    const int h     = bh & 15;
    const int tbase = split * TSPLIT;

    const float* kb = g_k + ((size_t)(b * T_ + tbase) * D_) + h * DK_;
    const float* vb = g_v + ((size_t)(b * T_ + tbase) * D_) + h * DK_;

    const int r0 = (tid >> 4) * 4;
    const int c0 = (tid & 15) * 4;
    const int lrow = tid >> 4;        // 0..15
    const int lc4  = (tid & 15) * 4;  // 0..60

    float acc[4][4];
#pragma unroll
    for (int i = 0; i < 4; i++)
#pragma unroll
        for (int j = 0; j < 4; j++) acc[i][j] = 0.f;
    float s = 0.f;

    for (int g = 0; g < TSPLIT / 16; g++) {
        __syncthreads();
        {
            float4 kk = *(const float4*)(kb + (size_t)(g * 16 + lrow) * D_ + lc4);
            float4 vv = *(const float4*)(vb + (size_t)(g * 16 + lrow) * D_ + lc4);
            *(float4*)&ks[lrow * 64 + lc4] = kk;
            *(float4*)&vs[lrow * 64 + lc4] = vv;
        }
        __syncthreads();
#pragma unroll
        for (int tt = 0; tt < 16; tt++) {
            float4 k4 = *(float4*)&ks[tt * 64 + r0];
            float4 v4 = *(float4*)&vs[tt * 64 + c0];
            float kr[4] = {k4.x, k4.y, k4.z, k4.w};
            float vc[4] = {v4.x, v4.y, v4.z, v4.w};
#pragma unroll
            for (int i = 0; i < 4; i++)
#pragma unroll
                for (int j = 0; j < 4; j++)
                    acc[i][j] = fmaf(kr[i], vc[j], acc[i][j]);
        }
        if (tid < 64) {
#pragma unroll
            for (int tt = 0; tt < 16; tt++) s += ks[tt * 64 + tid];
        }
    }

    float* dst = g_kvp + (size_t)split * (B_*H_*DK_*DK_) + (size_t)bh * (DK_*DK_);
#pragma unroll
    for (int i = 0; i < 4; i++)
#pragma unroll
        for (int j = 0; j < 4; j++)
            dst[(r0 + i) * DK_ + c0 + j] = acc[i][j];
    if (tid < 64)
        g_ksump[(size_t)split * (B_*H_*DK_) + bh * DK_ + tid] = s;
}

__global__ __launch_bounds__(256) void kv_reduce_kernel() {
    int i = blockIdx.x * 256 + threadIdx.x;
    if (i < B_*H_*DK_*DK_) {
        float s = 0.f;
#pragma unroll
        for (int sp = 0; sp < NSPLIT; sp++) s += g_kvp[(size_t)sp * (B_*H_*DK_*DK_) + i];
        g_kv[i] = s;
    }
    if (i < B_*H_*DK_) {
        float s = 0.f;
#pragma unroll
        for (int sp = 0; sp < NSPLIT; sp++) s += g_ksump[(size_t)sp * (B_*H_*DK_) + i];
        g_ksum[i] = s;
    }
}

// ---------------- attention apply ---------------------------------------------
__global__ __launch_bounds__(256) void attn_kernel() {
    __shared__ float qs[64 * 64];
    __shared__ float kvs[64 * 64];
    __shared__ float ksums[64];
    __shared__ float zs[64];

    const int tid = threadIdx.x;
    const int bh  = blockIdx.x;
    const int b   = bh >> 4;
    const int h   = bh & 15;
    const int t0  = blockIdx.y * 64;

    const float* qbase = g_q + ((size_t)(b * T_ + t0) * D_) + h * DK_;

    for (int i = tid; i < 4096; i += 256)
        kvs[i] = g_kv[(size_t)bh * 4096 + i];
    if (tid < 64)
        ksums[tid] = g_ksum[bh * DK_ + tid] + EPS;

    for (int i = tid; i < 1024; i += 256) {
        int t  = i >> 4;
        int c4 = (i & 15) * 4;
        float4 v = *(const float4*)(qbase + (size_t)t * D_ + c4);
        qs[(c4+0)*64 + t] = v.x;
        qs[(c4+1)*64 + t] = v.y;
        qs[(c4+2)*64 + t] = v.z;
        qs[(c4+3)*64 + t] = v.w;
    }
    __syncthreads();

    if (tid < 64) {
        float zn = 0.f;
#pragma unroll
        for (int d = 0; d < 64; d++) zn = fmaf(qs[d*64 + tid], ksums[d], zn);
        zs[tid] = 1.f / (zn + EPS);
    }
    __syncthreads();

    const int tx = tid & 15;
    const int ty = tid >> 4;
    float acc[4][4];
#pragma unroll
    for (int i = 0; i < 4; i++)
#pragma unroll
        for (int j = 0; j < 4; j++) acc[i][j] = 0.f;

#pragma unroll
    for (int d = 0; d < 64; d++) {
        float4 a4 = *(float4*)&qs[d*64 + ty*4];
        float4 b4 = *(float4*)&kvs[d*64 + tx*4];
        float a[4] = {a4.x, a4.y, a4.z, a4.w};
        float bb[4] = {b4.x, b4.y, b4.z, b4.w};
#pragma unroll
        for (int i = 0; i < 4; i++)
#pragma unroll
            for (int j = 0; j < 4; j++)
                acc[i][j] = fmaf(a[i], bb[j], acc[i][j]);
    }

#pragma unroll
    for (int i = 0; i < 4; i++) {
        int t = ty * 4 + i;
        float z = zs[t];
        float4 o = make_float4(acc[i][0]*z, acc[i][1]*z, acc[i][2]*z, acc[i][3]*z);
        *(float4*)&g_attn[(size_t)(b * T_ + t0 + t) * D_ + h * DK_ + tx * 4] = o;
    }
}

// ---------------- launch ----------------------------------------------------
extern "C" void kernel_launch(void* const* d_in, const int* in_sizes, int n_in,
                              void* d_out, int out_size) {
    const float* x  = (const float*)d_in[0];
    const float* Wq = (const float*)d_in[1];
    const float* bq = (const float*)d_in[2];
    const float* Wk = (const float*)d_in[3];
    const float* bk = (const float*)d_in[4];
    const float* Wv = (const float*)d_in[5];
    const float* bv = (const float*)d_in[6];
    const float* Wo = (const float*)d_in[7];
    const float* bo = (const float*)d_in[8];
    float* out = (float*)d_out;

    static bool attr_set = false;
    if (!attr_set) {
        cudaFuncSetAttribute(gemm_q_tc, cudaFuncAttributeMaxDynamicSharedMemorySize, GSMEM);
        cudaFuncSetAttribute(gemm_k_tc, cudaFuncAttributeMaxDynamicSharedMemorySize, GSMEM);
        cudaFuncSetAttribute(gemm_v_tc, cudaFuncAttributeMaxDynamicSharedMemorySize, GSMEM);
        cudaFuncSetAttribute(gemm_o_tc, cudaFuncAttributeMaxDynamicSharedMemorySize, GSMEM);
        attr_set = true;
    }

    dim3 gg(N_ / 128, M_ / 128);   // (8, 128)
    gemm_q_tc<<<gg, 256, GSMEM>>>(x, Wq, bq);
    gemm_k_tc<<<gg, 256, GSMEM>>>(x, Wk, bk);
    gemm_v_tc<<<gg, 256, GSMEM>>>(x, Wv, bv);
    kv_kernel<<<dim3(B_*H_, NSPLIT), 256>>>();
    kv_reduce_kernel<<<(B_*H_*DK_*DK_ + 255) / 256, 256>>>();
    attn_kernel<<<dim3(B_*H_, T_ / 64), 256>>>();
    gemm_o_tc<<<gg, 256, GSMEM>>>(Wo, bo, out);
}

// round 7
// speedup vs baseline: 2.8168x; 1.2372x over previous
#include <cuda_runtime.h>
#include <cuda_fp16.h>
#include <cstdint>

#define B_ 4
#define T_ 4096
#define D_ 1024
#define H_ 16
#define DK_ 64
#define M_ (B_*T_)          // 16384
#define K_ D_               // 1024
#define N_ D_               // 1024
#define EPS 1e-6f

#define NSPLIT 64
#define TSPLIT (T_/NSPLIT)  // 64

// ---------------- scratch (device globals; no allocations allowed) ----------
__device__ float g_q[M_*D_];
__device__ float g_k[M_*D_];
__device__ float g_v[M_*D_];
__device__ float g_attn[M_*D_];
__device__ float g_kvp[NSPLIT*B_*H_*DK_*DK_];
__device__ float g_ksump[NSPLIT*B_*H_*DK_];
__device__ float g_kv[B_*H_*DK_*DK_];
__device__ float g_ksum[B_*H_*DK_];

// ---------------- helpers -----------------------------------------------------
__device__ __forceinline__ uint32_t smem_u32(const void* p) {
    uint32_t a;
    asm("{ .reg .u64 t; cvta.to.shared.u64 t, %1; cvt.u32.u64 %0, t; }" : "=r"(a) : "l"(p));
    return a;
}

#define LDSM_X4(r, addr) \
    asm volatile("ldmatrix.sync.aligned.m8n8.x4.shared.b16 {%0,%1,%2,%3}, [%4];" \
        : "=r"((r)[0]), "=r"((r)[1]), "=r"((r)[2]), "=r"((r)[3]) : "r"(addr))

#define LDSM_X2(r, addr) \
    asm volatile("ldmatrix.sync.aligned.m8n8.x2.shared.b16 {%0,%1}, [%2];" \
        : "=r"((r)[0]), "=r"((r)[1]) : "r"(addr))

#define MMA_F16(d, a, b) \
    asm volatile("mma.sync.aligned.m16n8k16.row.col.f32.f16.f16.f32 " \
        "{%0,%1,%2,%3},{%4,%5,%6,%7},{%8,%9},{%0,%1,%2,%3};" \
        : "+f"((d)[0]), "+f"((d)[1]), "+f"((d)[2]), "+f"((d)[3]) \
        : "r"((a)[0]), "r"((a)[1]), "r"((a)[2]), "r"((a)[3]), \
          "r"((b)[0]), "r"((b)[1]))

template<int ACT>
__device__ __forceinline__ float actf(float v) {
    if (ACT == 1) return v > 0.f ? v + 1.f : __expf(v);   // elu(x)+1
    return v;
}

// split fp32 -> fp16 hi + fp16 lo (lo = rounded residual; ~22 bits total)
__device__ __forceinline__ void cvt_split_f16(float4 f, uint2& hi, uint2& lo) {
    __half2 h0 = __floats2half2_rn(f.x, f.y);
    __half2 h1 = __floats2half2_rn(f.z, f.w);
    float2 b0 = __half22float2(h0);
    float2 b1 = __half22float2(h1);
    __half2 l0 = __floats2half2_rn(f.x - b0.x, f.y - b0.y);
    __half2 l1 = __floats2half2_rn(f.z - b1.x, f.w - b1.y);
    hi.x = *(uint32_t*)&h0; hi.y = *(uint32_t*)&h1;
    lo.x = *(uint32_t*)&l0; lo.y = *(uint32_t*)&l1;
}

__device__ __forceinline__ uint2 cvt_hi_f16(float4 f) {
    __half2 h0 = __floats2half2_rn(f.x, f.y);
    __half2 h1 = __floats2half2_rn(f.z, f.w);
    uint2 r;
    r.x = *(uint32_t*)&h0; r.y = *(uint32_t*)&h1;
    return r;
}

// ---------------- HMMA GEMM: C = act(A @ W^T + bias) --------------------------
// A:[M_,K_], W:[N_,K_] fp32. A split fp16 hi+lo, W fp16 hi only.
// C ~= Ahi*Whi + Alo*Whi  (dropped Ahi*Wlo ~ 2^-12 rel). 2 MMA products.
// CTA tile 128x128, 8 warps (2x4), warp tile 64x32, BK=32 floats.
#define BKF 32
#define NCHUNK (K_/BKF)      // 32
#define PADB 80              // bytes per smem row (40 fp16) - conflict-free ldmatrix
#define TILE_B (128*PADB)    // 10240
#define STAGE_B (3*TILE_B)   // Ahi, Alo, Whi = 30720
#define GSMEM (2*STAGE_B)    // 61440

__device__ __forceinline__ void load_g(const float* __restrict__ A,
                                       const float* __restrict__ W,
                                       int m0, int n0, int kc, int tid,
                                       float4* sa, float4* sw) {
#pragma unroll
    for (int j = 0; j < 4; j++) {
        int idx = tid + j * 256;
        int r   = idx >> 3;
        int c4  = (idx & 7) << 2;
        sa[j] = *(const float4*)(A + (size_t)(m0 + r) * K_ + kc * BKF + c4);
        sw[j] = *(const float4*)(W + (size_t)(n0 + r) * K_ + kc * BKF + c4);
    }
}

__device__ __forceinline__ void store_s(char* base, int tid,
                                        const float4* sa, const float4* sw) {
#pragma unroll
    for (int j = 0; j < 4; j++) {
        int idx = tid + j * 256;
        int r   = idx >> 3;
        int c4  = (idx & 7) << 2;
        int off = r * PADB + (c4 << 1);
        uint2 hi, lo;
        cvt_split_f16(sa[j], hi, lo);
        *(uint2*)(base + off)          = hi;
        *(uint2*)(base + TILE_B + off) = lo;
        *(uint2*)(base + 2*TILE_B + off) = cvt_hi_f16(sw[j]);
    }
}

template<int ACT>
__device__ __forceinline__ void gemm_body(const float* __restrict__ A,
                                          const float* __restrict__ W,
                                          const float* __restrict__ bias,
                                          float* __restrict__ C) {
    extern __shared__ char smem[];
    const int tid    = threadIdx.x;
    const int lane   = tid & 31;
    const int wid    = tid >> 5;
    const int warp_m = wid >> 2;       // 0..1
    const int warp_n = wid & 3;        // 0..3
    const int m0     = blockIdx.y * 128;
    const int n0     = blockIdx.x * 128;
    const uint32_t sbase = smem_u32(smem);

    float acc[4][4][4];
#pragma unroll
    for (int mi = 0; mi < 4; mi++)
#pragma unroll
        for (int ni = 0; ni < 4; ni++)
#pragma unroll
            for (int t = 0; t < 4; t++) acc[mi][ni][t] = 0.f;

    float4 sa[4], sw4[4];
    load_g(A, W, m0, n0, 0, tid, sa, sw4);
    store_s(smem, tid, sa, sw4);
    __syncthreads();

    int p = 0;
    for (int kc = 0; kc < NCHUNK; kc++) {
        const bool pre = (kc + 1) < NCHUNK;
        if (pre) load_g(A, W, m0, n0, kc + 1, tid, sa, sw4);

        const uint32_t base = sbase + p * STAGE_B;

#pragma unroll
        for (int ks = 0; ks < 2; ks++) {
            // ---- B hi fragments for 4 n-tiles ----
            uint32_t bhi[4][2];
            const int l2   = lane & 15;
            const int bk   = ks * 32 + ((l2 >> 3) & 1) * 16;
            const int brow = warp_n * 32 + (l2 & 7);
#pragma unroll
            for (int ni = 0; ni < 4; ni++) {
                uint32_t addr = base + 2*TILE_B + (uint32_t)(brow + ni * 8) * PADB + bk;
                LDSM_X2(bhi[ni], addr);
            }
            // ---- A hi/lo fragments ----
            const int arow = warp_m * 64 + (lane & 15);
            const int ak   = ks * 32 + (lane >> 4) * 16;
            uint32_t ah[4][4], al[4][4];
#pragma unroll
            for (int mi = 0; mi < 4; mi++) {
                uint32_t aaddr = base + (uint32_t)(arow + mi * 16) * PADB + ak;
                LDSM_X4(ah[mi], aaddr);
                LDSM_X4(al[mi], aaddr + TILE_B);
            }
            // ---- 2-product MMA, product-outermost ----
#pragma unroll
            for (int mi = 0; mi < 4; mi++)
#pragma unroll
                for (int ni = 0; ni < 4; ni++)
                    MMA_F16(acc[mi][ni], ah[mi], bhi[ni]);
#pragma unroll
            for (int mi = 0; mi < 4; mi++)
#pragma unroll
                for (int ni = 0; ni < 4; ni++)
                    MMA_F16(acc[mi][ni], al[mi], bhi[ni]);
        }

        if (pre) store_s(smem + (p ^ 1) * STAGE_B, tid, sa, sw4);
        __syncthreads();
        p ^= 1;
    }

    // ---- epilogue: bias + activation ----
#pragma unroll
    for (int mi = 0; mi < 4; mi++) {
        int r0 = m0 + warp_m * 64 + mi * 16 + (lane >> 2);
#pragma unroll
        for (int ni = 0; ni < 4; ni++) {
            int c = n0 + warp_n * 32 + ni * 8 + (lane & 3) * 2;
            float b0v = bias[c], b1v = bias[c + 1];
            float2 o0, o1;
            o0.x = actf<ACT>(acc[mi][ni][0] + b0v);
            o0.y = actf<ACT>(acc[mi][ni][1] + b1v);
            o1.x = actf<ACT>(acc[mi][ni][2] + b0v);
            o1.y = actf<ACT>(acc[mi][ni][3] + b1v);
            *(float2*)&C[(size_t)r0 * N_ + c]       = o0;
            *(float2*)&C[(size_t)(r0 + 8) * N_ + c] = o1;
        }
    }
}

__global__ void __launch_bounds__(256, 1)
gemm_q_tc(const float* __restrict__ A, const float* __restrict__ W, const float* __restrict__ b) {
    gemm_body<1>(A, W, b, g_q);
}
__global__ void __launch_bounds__(256, 1)
gemm_k_tc(const float* __restrict__ A, const float* __restrict__ W, const float* __restrict__ b) {
    gemm_body<1>(A, W, b, g_k);
}
__global__ void __launch_bounds__(256, 1)
gemm_v_tc(const float* __restrict__ A, const float* __restrict__ W, const float* __restrict__ b) {
    gemm_body<0>(A, W, b, g_v);
}
__global__ void __launch_bounds__(256, 1)
gemm_o_tc(const float* __restrict__ W, const float* __restrict__ b, float* __restrict__ out) {
    gemm_body<0>(g_attn, W, b, out);
}

// ---------------- kv summary (split partials, deterministic) ------------------
__global__ __launch_bounds__(256) void kv_kernel() {
    __shared__ float ks[16 * 64];
    __shared__ float vs[16 * 64];
    const int tid   = threadIdx.x;
    const int bh    = blockIdx.x;
    const int split = blockIdx.y;
    const int b     = bh >> 4;
    const int h     = bh & 15;
    const int tbase = split * TSPLIT;

    const float* kb = g_k + ((size_t)(b * T_ + tbase) * D_) + h * DK_;
    const float* vb = g_v + ((size_t)(b * T_ + tbase) * D_) + h * DK_;

    const int r0 = (tid >> 4) * 4;
    const int c0 = (tid & 15) * 4;
    const int lrow = tid >> 4;        // 0..15
    const int lc4  = (tid & 15) * 4;  // 0..60

    float acc[4][4];
#pragma unroll
    for (int i = 0; i < 4; i++)
#pragma unroll
        for (int j = 0; j < 4; j++) acc[i][j] = 0.f;
    float s = 0.f;

    for (int g = 0; g < TSPLIT / 16; g++) {
        __syncthreads();
        {
            float4 kk = *(const float4*)(kb + (size_t)(g * 16 + lrow) * D_ + lc4);
            float4 vv = *(const float4*)(vb + (size_t)(g * 16 + lrow) * D_ + lc4);
            *(float4*)&ks[lrow * 64 + lc4] = kk;
            *(float4*)&vs[lrow * 64 + lc4] = vv;
        }
        __syncthreads();
#pragma unroll
        for (int tt = 0; tt < 16; tt++) {
            float4 k4 = *(float4*)&ks[tt * 64 + r0];
            float4 v4 = *(float4*)&vs[tt * 64 + c0];
            float kr[4] = {k4.x, k4.y, k4.z, k4.w};
            float vc[4] = {v4.x, v4.y, v4.z, v4.w};
#pragma unroll
            for (int i = 0; i < 4; i++)
#pragma unroll
                for (int j = 0; j < 4; j++)
                    acc[i][j] = fmaf(kr[i], vc[j], acc[i][j]);
        }
        if (tid < 64) {
#pragma unroll
            for (int tt = 0; tt < 16; tt++) s += ks[tt * 64 + tid];
        }
    }

    float* dst = g_kvp + (size_t)split * (B_*H_*DK_*DK_) + (size_t)bh * (DK_*DK_);
#pragma unroll
    for (int i = 0; i < 4; i++)
#pragma unroll
        for (int j = 0; j < 4; j++)
            dst[(r0 + i) * DK_ + c0 + j] = acc[i][j];
    if (tid < 64)
        g_ksump[(size_t)split * (B_*H_*DK_) + bh * DK_ + tid] = s;
}

__global__ __launch_bounds__(256) void kv_reduce_kernel() {
    int i = blockIdx.x * 256 + threadIdx.x;
    if (i < B_*H_*DK_*DK_) {
        float s = 0.f;
#pragma unroll
        for (int sp = 0; sp < NSPLIT; sp++) s += g_kvp[(size_t)sp * (B_*H_*DK_*DK_) + i];
        g_kv[i] = s;
    }
    if (i < B_*H_*DK_) {
        float s = 0.f;
#pragma unroll
        for (int sp = 0; sp < NSPLIT; sp++) s += g_ksump[(size_t)sp * (B_*H_*DK_) + i];
        g_ksum[i] = s;
    }
}

// ---------------- attention apply ---------------------------------------------
__global__ __launch_bounds__(256) void attn_kernel() {
    __shared__ float qs[64 * 64];
    __shared__ float kvs[64 * 64];
    __shared__ float ksums[64];
    __shared__ float zs[64];

    const int tid = threadIdx.x;
    const int bh  = blockIdx.x;
    const int b   = bh >> 4;
    const int h   = bh & 15;
    const int t0  = blockIdx.y * 64;

    const float* qbase = g_q + ((size_t)(b * T_ + t0) * D_) + h * DK_;

    for (int i = tid; i < 4096; i += 256)
        kvs[i] = g_kv[(size_t)bh * 4096 + i];
    if (tid < 64)
        ksums[tid] = g_ksum[bh * DK_ + tid] + EPS;

    for (int i = tid; i < 1024; i += 256) {
        int t  = i >> 4;
        int c4 = (i & 15) * 4;
        float4 v = *(const float4*)(qbase + (size_t)t * D_ + c4);
        qs[(c4+0)*64 + t] = v.x;
        qs[(c4+1)*64 + t] = v.y;
        qs[(c4+2)*64 + t] = v.z;
        qs[(c4+3)*64 + t] = v.w;
    }
    __syncthreads();

    if (tid < 64) {
        float zn = 0.f;
#pragma unroll
        for (int d = 0; d < 64; d++) zn = fmaf(qs[d*64 + tid], ksums[d], zn);
        zs[tid] = 1.f / (zn + EPS);
    }
    __syncthreads();

    const int tx = tid & 15;
    const int ty = tid >> 4;
    float acc[4][4];
#pragma unroll
    for (int i = 0; i < 4; i++)
#pragma unroll
        for (int j = 0; j < 4; j++) acc[i][j] = 0.f;

#pragma unroll
    for (int d = 0; d < 64; d++) {
        float4 a4 = *(float4*)&qs[d*64 + ty*4];
        float4 b4 = *(float4*)&kvs[d*64 + tx*4];
        float a[4] = {a4.x, a4.y, a4.z, a4.w};
        float bb[4] = {b4.x, b4.y, b4.z, b4.w};
#pragma unroll
        for (int i = 0; i < 4; i++)
#pragma unroll
            for (int j = 0; j < 4; j++)
                acc[i][j] = fmaf(a[i], bb[j], acc[i][j]);
    }

#pragma unroll
    for (int i = 0; i < 4; i++) {
        int t = ty * 4 + i;
        float z = zs[t];
        float4 o = make_float4(acc[i][0]*z, acc[i][1]*z, acc[i][2]*z, acc[i][3]*z);
        *(float4*)&g_attn[(size_t)(b * T_ + t0 + t) * D_ + h * DK_ + tx * 4] = o;
    }
}

// ---------------- launch ----------------------------------------------------
extern "C" void kernel_launch(void* const* d_in, const int* in_sizes, int n_in,
                              void* d_out, int out_size) {
    const float* x  = (const float*)d_in[0];
    const float* Wq = (const float*)d_in[1];
    const float* bq = (const float*)d_in[2];
    const float* Wk = (const float*)d_in[3];
    const float* bk = (const float*)d_in[4];
    const float* Wv = (const float*)d_in[5];
    const float* bv = (const float*)d_in[6];
    const float* Wo = (const float*)d_in[7];
    const float* bo = (const float*)d_in[8];
    float* out = (float*)d_out;

    static bool attr_set = false;
    if (!attr_set) {
        cudaFuncSetAttribute(gemm_q_tc, cudaFuncAttributeMaxDynamicSharedMemorySize, GSMEM);
        cudaFuncSetAttribute(gemm_k_tc, cudaFuncAttributeMaxDynamicSharedMemorySize, GSMEM);
        cudaFuncSetAttribute(gemm_v_tc, cudaFuncAttributeMaxDynamicSharedMemorySize, GSMEM);
        cudaFuncSetAttribute(gemm_o_tc, cudaFuncAttributeMaxDynamicSharedMemorySize, GSMEM);
        attr_set = true;
    }

    dim3 gg(N_ / 128, M_ / 128);   // (8, 128)
    gemm_q_tc<<<gg, 256, GSMEM>>>(x, Wq, bq);
    gemm_k_tc<<<gg, 256, GSMEM>>>(x, Wk, bk);
    gemm_v_tc<<<gg, 256, GSMEM>>>(x, Wv, bv);
    kv_kernel<<<dim3(B_*H_, NSPLIT), 256>>>();
    kv_reduce_kernel<<<(B_*H_*DK_*DK_ + 255) / 256, 256>>>();
    attn_kernel<<<dim3(B_*H_, T_ / 64), 256>>>();
    gemm_o_tc<<<gg, 256, GSMEM>>>(Wo, bo, out);
}

// round 10
// speedup vs baseline: 2.9809x; 1.0583x over previous
#include <cuda_runtime.h>
#include <cuda_fp16.h>
#include <cstdint>

#define B_ 4
#define T_ 4096
#define D_ 1024
#define H_ 16
#define DK_ 64
#define M_ (B_*T_)          // 16384
#define K_ D_               // 1024
#define N_ D_               // 1024
#define EPS 1e-6f

#define NSPLIT 64
#define TSPLIT (T_/NSPLIT)  // 64

// ---------------- scratch (device globals; no allocations allowed) ----------
__device__ float g_q[M_*D_];
__device__ float g_k[M_*D_];
__device__ float g_v[M_*D_];
__device__ __half g_xhi[M_*D_];
__device__ __half g_xlo[M_*D_];
__device__ __half g_whi[4*D_*D_];     // Wq, Wk, Wv, Wo (hi halves)
__device__ __half g_ahi[M_*D_];       // attn output hi
__device__ __half g_alo[M_*D_];       // attn output lo
__device__ float g_kvp[NSPLIT*B_*H_*DK_*DK_];
__device__ float g_ksump[NSPLIT*B_*H_*DK_];
__device__ float g_kv[B_*H_*DK_*DK_];
__device__ float g_ksum[B_*H_*DK_];

// ---------------- helpers -----------------------------------------------------
__device__ __forceinline__ uint32_t smem_u32(const void* p) {
    uint32_t a;
    asm("{ .reg .u64 t; cvta.to.shared.u64 t, %1; cvt.u32.u64 %0, t; }" : "=r"(a) : "l"(p));
    return a;
}

#define LDSM_X4(r, addr) \
    asm volatile("ldmatrix.sync.aligned.m8n8.x4.shared.b16 {%0,%1,%2,%3}, [%4];" \
        : "=r"((r)[0]), "=r"((r)[1]), "=r"((r)[2]), "=r"((r)[3]) : "r"(addr))

#define LDSM_X2(r, addr) \
    asm volatile("ldmatrix.sync.aligned.m8n8.x2.shared.b16 {%0,%1}, [%2];" \
        : "=r"((r)[0]), "=r"((r)[1]) : "r"(addr))

#define MMA_F16(d, a, b) \
    asm volatile("mma.sync.aligned.m16n8k16.row.col.f32.f16.f16.f32 " \
        "{%0,%1,%2,%3},{%4,%5,%6,%7},{%8,%9},{%0,%1,%2,%3};" \
        : "+f"((d)[0]), "+f"((d)[1]), "+f"((d)[2]), "+f"((d)[3]) \
        : "r"((a)[0]), "r"((a)[1]), "r"((a)[2]), "r"((a)[3]), \
          "r"((b)[0]), "r"((b)[1]))

#define CP_ASYNC16(dst_u32, src_gptr) \
    asm volatile("cp.async.cg.shared.global [%0], [%1], 16;" \
        :: "r"(dst_u32), "l"(src_gptr))

#define CP_COMMIT() asm volatile("cp.async.commit_group;")
#define CP_WAIT1()  asm volatile("cp.async.wait_group 1;")

template<int ACT>
__device__ __forceinline__ float actf(float v) {
    if (ACT == 1) return v > 0.f ? v + 1.f : __expf(v);   // elu(x)+1
    return v;
}

// ---------------- pre-conversion kernels --------------------------------------
// x: fp32 -> hi/lo fp16 split
__global__ __launch_bounds__(256) void cvt_x_kernel(const float* __restrict__ x) {
    int i = blockIdx.x * 256 + threadIdx.x;          // float4 index
    float4 f = ((const float4*)x)[i];
    __half2 h0 = __floats2half2_rn(f.x, f.y);
    __half2 h1 = __floats2half2_rn(f.z, f.w);
    float2 b0 = __half22float2(h0);
    float2 b1 = __half22float2(h1);
    __half2 l0 = __floats2half2_rn(f.x - b0.x, f.y - b0.y);
    __half2 l1 = __floats2half2_rn(f.z - b1.x, f.w - b1.y);
    uint2 hi, lo;
    hi.x = *(uint32_t*)&h0; hi.y = *(uint32_t*)&h1;
    lo.x = *(uint32_t*)&l0; lo.y = *(uint32_t*)&l1;
    ((uint2*)g_xhi)[i] = hi;
    ((uint2*)g_xlo)[i] = lo;
}

// W: fp32 -> hi fp16 only
__global__ __launch_bounds__(256) void cvt_w_kernel(const float* __restrict__ W, int slot) {
    int i = blockIdx.x * 256 + threadIdx.x;          // float4 index
    float4 f = ((const float4*)W)[i];
    __half2 h0 = __floats2half2_rn(f.x, f.y);
    __half2 h1 = __floats2half2_rn(f.z, f.w);
    uint2 hi;
    hi.x = *(uint32_t*)&h0; hi.y = *(uint32_t*)&h1;
    ((uint2*)(g_whi + (size_t)slot * D_ * D_))[i] = hi;
}

// ---------------- HMMA GEMM: C = act(Ahi/lo @ Whi^T + bias) -------------------
// Pre-split fp16 inputs, cp.async 3-stage pipeline, 2 CTAs/SM.
// CTA tile 128x128, 8 warps (2x4), warp tile 64x32, BK=32.
#define BKF 32
#define NCHUNK (K_/BKF)      // 32
#define PADB 80              // bytes per smem row (40 fp16) - conflict-free ldmatrix
#define TILE_B (128*PADB)    // 10240
#define STAGE_B (3*TILE_B)   // Ahi, Alo, Whi
#define NSTAGE 3
#define GSMEM (NSTAGE*STAGE_B)   // 92160

// issue one stage: 3 tiles x 128 rows x 64B. 6 cp.async per thread, branch-free
// (j<2 -> Ahi, j in {2,3} -> Alo, j in {4,5} -> Whi).
__device__ __forceinline__ void issue_stage(const __half* __restrict__ Ahi,
                                            const __half* __restrict__ Alo,
                                            const __half* __restrict__ Whi,
                                            int m0, int n0, int kc,
                                            uint32_t stage_u, int tid, bool live) {
    if (live) {
        const int kb = kc * BKF;
#pragma unroll
        for (int j = 0; j < 6; j++) {
            int seg  = tid + j * 256;          // 0..1535
            int rem  = seg & 511;
            int row  = rem >> 2;
            int s4   = rem & 3;
            const __half* src;
            uint32_t dst;
            if (j < 2) {
                src = Ahi + (size_t)(m0 + row) * K_ + kb + s4 * 8;
                dst = stage_u + row * PADB + s4 * 16;
            } else if (j < 4) {
                src = Alo + (size_t)(m0 + row) * K_ + kb + s4 * 8;
                dst = stage_u + TILE_B + row * PADB + s4 * 16;
            } else {
                src = Whi + (size_t)(n0 + row) * K_ + kb + s4 * 8;
                dst = stage_u + 2 * TILE_B + row * PADB + s4 * 16;
            }
            CP_ASYNC16(dst, src);
        }
    }
    CP_COMMIT();   // empty group when !live keeps wait_group bookkeeping uniform
}

template<int ACT>
__device__ __forceinline__ void gemm_body(const __half* __restrict__ Ahi,
                                          const __half* __restrict__ Alo,
                                          const __half* __restrict__ Whi,
                                          const float* __restrict__ bias,
                                          float* __restrict__ C) {
    extern __shared__ char smem[];
    const int tid    = threadIdx.x;
    const int lane   = tid & 31;
    const int wid    = tid >> 5;
    const int warp_m = wid >> 2;       // 0..1
    const int warp_n = wid & 3;        // 0..3
    const int m0     = blockIdx.y * 128;
    const int n0     = blockIdx.x * 128;
    const uint32_t sbase = smem_u32(smem);

    float acc[4][4][4];
#pragma unroll
    for (int mi = 0; mi < 4; mi++)
#pragma unroll
        for (int ni = 0; ni < 4; ni++)
#pragma unroll
            for (int t = 0; t < 4; t++) acc[mi][ni][t] = 0.f;

    issue_stage(Ahi, Alo, Whi, m0, n0, 0, sbase,               tid, true);
    issue_stage(Ahi, Alo, Whi, m0, n0, 1, sbase + STAGE_B,     tid, true);

    int stage = 0;
    for (int kc = 0; kc < NCHUNK; kc++) {
        CP_WAIT1();            // oldest group (stage for kc) complete
        __syncthreads();       // all threads' groups visible; all warps past kc-1

        int nst = stage + 2; if (nst >= NSTAGE) nst -= NSTAGE;
        issue_stage(Ahi, Alo, Whi, m0, n0, kc + 2, sbase + nst * STAGE_B,
                    tid, kc + 2 < NCHUNK);

        const uint32_t base = sbase + stage * STAGE_B;

#pragma unroll
        for (int ks = 0; ks < 2; ks++) {
            uint32_t bhi[4][2];
            const int l2   = lane & 15;
            const int bk   = ks * 32 + ((l2 >> 3) & 1) * 16;
            const int brow = warp_n * 32 + (l2 & 7);
#pragma unroll
            for (int ni = 0; ni < 4; ni++) {
                uint32_t addr = base + 2*TILE_B + (uint32_t)(brow + ni * 8) * PADB + bk;
                LDSM_X2(bhi[ni], addr);
            }
            const int arow = warp_m * 64 + (lane & 15);
            const int ak   = ks * 32 + (lane >> 4) * 16;
            uint32_t ah[4][4], al[4][4];
#pragma unroll
            for (int mi = 0; mi < 4; mi++) {
                uint32_t aaddr = base + (uint32_t)(arow + mi * 16) * PADB + ak;
                LDSM_X4(ah[mi], aaddr);
                LDSM_X4(al[mi], aaddr + TILE_B);
            }
#pragma unroll
            for (int mi = 0; mi < 4; mi++)
#pragma unroll
                for (int ni = 0; ni < 4; ni++)
                    MMA_F16(acc[mi][ni], ah[mi], bhi[ni]);
#pragma unroll
            for (int mi = 0; mi < 4; mi++)
#pragma unroll
                for (int ni = 0; ni < 4; ni++)
                    MMA_F16(acc[mi][ni], al[mi], bhi[ni]);
        }

        if (++stage >= NSTAGE) stage = 0;
    }

    // ---- epilogue: bias + activation ----
#pragma unroll
    for (int mi = 0; mi < 4; mi++) {
        int r0 = m0 + warp_m * 64 + mi * 16 + (lane >> 2);
#pragma unroll
        for (int ni = 0; ni < 4; ni++) {
            int c = n0 + warp_n * 32 + ni * 8 + (lane & 3) * 2;
            float b0v = bias[c], b1v = bias[c + 1];
            float2 o0, o1;
            o0.x = actf<ACT>(acc[mi][ni][0] + b0v);
            o0.y = actf<ACT>(acc[mi][ni][1] + b1v);
            o1.x = actf<ACT>(acc[mi][ni][2] + b0v);
            o1.y = actf<ACT>(acc[mi][ni][3] + b1v);
            *(float2*)&C[(size_t)r0 * N_ + c]       = o0;
            *(float2*)&C[(size_t)(r0 + 8) * N_ + c] = o1;
        }
    }
}

__global__ void __launch_bounds__(256, 2)
gemm_q_tc(const float* __restrict__ b) {
    gemm_body<1>(g_xhi, g_xlo, g_whi, b, g_q);
}
__global__ void __launch_bounds__(256, 2)
gemm_k_tc(const float* __restrict__ b) {
    gemm_body<1>(g_xhi, g_xlo, g_whi + (size_t)D_*D_, b, g_k);
}
__global__ void __launch_bounds__(256, 2)
gemm_v_tc(const float* __restrict__ b) {
    gemm_body<0>(g_xhi, g_xlo, g_whi + (size_t)2*D_*D_, b, g_v);
}
__global__ void __launch_bounds__(256, 2)
gemm_o_tc(const float* __restrict__ b, float* __restrict__ out) {
    gemm_body<0>(g_ahi, g_alo, g_whi + (size_t)3*D_*D_, b, out);
}

// ---------------- kv summary (split partials, deterministic) ------------------
__global__ __launch_bounds__(256) void kv_kernel() {
    __shared__ float ks[16 * 64];
    __shared__ float vs[16 * 64];
    const int tid   = threadIdx.x;
    const int bh    = blockIdx.x;
    const int split = blockIdx.y;
    const int b     = bh >> 4;
    const int h     = bh & 15;
    const int tbase = split * TSPLIT;

    const float* kb = g_k + ((size_t)(b * T_ + tbase) * D_) + h * DK_;
    const float* vb = g_v + ((size_t)(b * T_ + tbase) * D_) + h * DK_;

    const int r0 = (tid >> 4) * 4;
    const int c0 = (tid & 15) * 4;
    const int lrow = tid >> 4;
    const int lc4  = (tid & 15) * 4;

    float acc[4][4];
#pragma unroll
    for (int i = 0; i < 4; i++)
#pragma unroll
        for (int j = 0; j < 4; j++) acc[i][j] = 0.f;
    float s = 0.f;

    for (int g = 0; g < TSPLIT / 16; g++) {
        __syncthreads();
        {
            float4 kk = *(const float4*)(kb + (size_t)(g * 16 + lrow) * D_ + lc4);
            float4 vv = *(const float4*)(vb + (size_t)(g * 16 + lrow) * D_ + lc4);
            *(float4*)&ks[lrow * 64 + lc4] = kk;
            *(float4*)&vs[lrow * 64 + lc4] = vv;
        }
        __syncthreads();
#pragma unroll
        for (int tt = 0; tt < 16; tt++) {
            float4 k4 = *(float4*)&ks[tt * 64 + r0];
            float4 v4 = *(float4*)&vs[tt * 64 + c0];
            float kr[4] = {k4.x, k4.y, k4.z, k4.w};
            float vc[4] = {v4.x, v4.y, v4.z, v4.w};
#pragma unroll
            for (int i = 0; i < 4; i++)
#pragma unroll
                for (int j = 0; j < 4; j++)
                    acc[i][j] = fmaf(kr[i], vc[j], acc[i][j]);
        }
        if (tid < 64) {
#pragma unroll
            for (int tt = 0; tt < 16; tt++) s += ks[tt * 64 + tid];
        }
    }

    float* dst = g_kvp + (size_t)split * (B_*H_*DK_*DK_) + (size_t)bh * (DK_*DK_);
#pragma unroll
    for (int i = 0; i < 4; i++)
#pragma unroll
        for (int j = 0; j < 4; j++)
            dst[(r0 + i) * DK_ + c0 + j] = acc[i][j];
    if (tid < 64)
        g_ksump[(size_t)split * (B_*H_*DK_) + bh * DK_ + tid] = s;
}

__global__ __launch_bounds__(256) void kv_reduce_kernel() {
    int i = blockIdx.x * 256 + threadIdx.x;
    if (i < B_*H_*DK_*DK_) {
        float s = 0.f;
#pragma unroll
        for (int sp = 0; sp < NSPLIT; sp++) s += g_kvp[(size_t)sp * (B_*H_*DK_*DK_) + i];
        g_kv[i] = s;
    }
    if (i < B_*H_*DK_) {
        float s = 0.f;
#pragma unroll
        for (int sp = 0; sp < NSPLIT; sp++) s += g_ksump[(size_t)sp * (B_*H_*DK_) + i];
        g_ksum[i] = s;
    }
}

// ---------------- attention apply (emits hi/lo fp16 for O-GEMM) ---------------
__global__ __launch_bounds__(256) void attn_kernel() {
    __shared__ float qs[64 * 64];
    __shared__ float kvs[64 * 64];
    __shared__ float ksums[64];
    __shared__ float zs[64];

    const int tid = threadIdx.x;
    const int bh  = blockIdx.x;
    const int b   = bh >> 4;
    const int h   = bh & 15;
    const int t0  = blockIdx.y * 64;

    const float* qbase = g_q + ((size_t)(b * T_ + t0) * D_) + h * DK_;

    for (int i = tid; i < 4096; i += 256)
        kvs[i] = g_kv[(size_t)bh * 4096 + i];
    if (tid < 64)
        ksums[tid] = g_ksum[bh * DK_ + tid] + EPS;

    for (int i = tid; i < 1024; i += 256) {
        int t  = i >> 4;
        int c4 = (i & 15) * 4;
        float4 v = *(const float4*)(qbase + (size_t)t * D_ + c4);
        qs[(c4+0)*64 + t] = v.x;
        qs[(c4+1)*64 + t] = v.y;
        qs[(c4+2)*64 + t] = v.z;
        qs[(c4+3)*64 + t] = v.w;
    }
    __syncthreads();

    if (tid < 64) {
        float zn = 0.f;
#pragma unroll
        for (int d = 0; d < 64; d++) zn = fmaf(qs[d*64 + tid], ksums[d], zn);
        zs[tid] = 1.f / (zn + EPS);
    }
    __syncthreads();

    const int tx = tid & 15;
    const int ty = tid >> 4;
    float acc[4][4];
#pragma unroll
    for (int i = 0; i < 4; i++)
#pragma unroll
        for (int j = 0; j < 4; j++) acc[i][j] = 0.f;

#pragma unroll
    for (int d = 0; d < 64; d++) {
        float4 a4 = *(float4*)&qs[d*64 + ty*4];
        float4 b4 = *(float4*)&kvs[d*64 + tx*4];
        float a[4] = {a4.x, a4.y, a4.z, a4.w};
        float bb[4] = {b4.x, b4.y, b4.z, b4.w};
#pragma unroll
        for (int i = 0; i < 4; i++)
#pragma unroll
            for (int j = 0; j < 4; j++)
                acc[i][j] = fmaf(a[i], bb[j], acc[i][j]);
    }

#pragma unroll
    for (int i = 0; i < 4; i++) {
        int t = ty * 4 + i;
        float z = zs[t];
        float o0 = acc[i][0]*z, o1 = acc[i][1]*z, o2 = acc[i][2]*z, o3 = acc[i][3]*z;
        __half2 h0 = __floats2half2_rn(o0, o1);
        __half2 h1 = __floats2half2_rn(o2, o3);
        float2 hb0 = __half22float2(h0);
        float2 hb1 = __half22float2(h1);
        __half2 l0 = __floats2half2_rn(o0 - hb0.x, o1 - hb0.y);
        __half2 l1 = __floats2half2_rn(o2 - hb1.x, o3 - hb1.y);
        size_t off = (size_t)(b * T_ + t0 + t) * D_ + h * DK_ + tx * 4;
        uint2 hi; hi.x = *(uint32_t*)&h0; hi.y = *(uint32_t*)&h1;
        uint2 lo; lo.x = *(uint32_t*)&l0; lo.y = *(uint32_t*)&l1;
        *(uint2*)(g_ahi + off) = hi;
        *(uint2*)(g_alo + off) = lo;
    }
}

// ---------------- launch ----------------------------------------------------
extern "C" void kernel_launch(void* const* d_in, const int* in_sizes, int n_in,
                              void* d_out, int out_size) {
    const float* x  = (const float*)d_in[0];
    const float* Wq = (const float*)d_in[1];
    const float* bq = (const float*)d_in[2];
    const float* Wk = (const float*)d_in[3];
    const float* bk = (const float*)d_in[4];
    const float* Wv = (const float*)d_in[5];
    const float* bv = (const float*)d_in[6];
    const float* Wo = (const float*)d_in[7];
    const float* bo = (const float*)d_in[8];
    float* out = (float*)d_out;

    static bool attr_set = false;
    if (!attr_set) {
        cudaFuncSetAttribute(gemm_q_tc, cudaFuncAttributeMaxDynamicSharedMemorySize, GSMEM);
        cudaFuncSetAttribute(gemm_k_tc, cudaFuncAttributeMaxDynamicSharedMemorySize, GSMEM);
        cudaFuncSetAttribute(gemm_v_tc, cudaFuncAttributeMaxDynamicSharedMemorySize, GSMEM);
        cudaFuncSetAttribute(gemm_o_tc, cudaFuncAttributeMaxDynamicSharedMemorySize, GSMEM);
        attr_set = true;
    }

    // launches 0-4 are converters so ncu's fixed "-s 5" lands on gemm_q_tc
    cvt_x_kernel<<<M_*D_/4/256, 256>>>(x);        // 0
    cvt_w_kernel<<<D_*D_/4/256, 256>>>(Wq, 0);    // 1
    cvt_w_kernel<<<D_*D_/4/256, 256>>>(Wk, 1);    // 2
    cvt_w_kernel<<<D_*D_/4/256, 256>>>(Wv, 2);    // 3
    cvt_w_kernel<<<D_*D_/4/256, 256>>>(Wo, 3);    // 4

    dim3 gg(N_ / 128, M_ / 128);   // (8, 128)
    gemm_q_tc<<<gg, 256, GSMEM>>>(bq);            // 5  <- profiled
    gemm_k_tc<<<gg, 256, GSMEM>>>(bk);
    gemm_v_tc<<<gg, 256, GSMEM>>>(bv);
    kv_kernel<<<dim3(B_*H_, NSPLIT), 256>>>();
    kv_reduce_kernel<<<(B_*H_*DK_*DK_ + 255) / 256, 256>>>();
    attn_kernel<<<dim3(B_*H_, T_ / 64), 256>>>();
    gemm_o_tc<<<gg, 256, GSMEM>>>(bo, out);
}

// round 12
// speedup vs baseline: 4.5009x; 1.5099x over previous
#include <cuda_runtime.h>
#include <cuda_fp16.h>
#include <cstdint>

#define B_ 4
#define T_ 4096
#define D_ 1024
#define H_ 16
#define DK_ 64
#define M_ (B_*T_)          // 16384
#define K_ D_               // 1024
#define N_ D_               // 1024
#define EPS 1e-6f

#define NSPLIT 64
#define TSPLIT (T_/NSPLIT)  // 64

// ---------------- scratch (device globals; no allocations allowed) ----------
__device__ float g_q[M_*D_];
__device__ float g_k[M_*D_];
__device__ float g_v[M_*D_];
__device__ __half g_xhi[M_*D_];
__device__ __half g_whi[4*D_*D_];     // Wq, Wk, Wv, Wo (fp16)
__device__ __half g_ahi[M_*D_];       // attn output fp16
__device__ float g_kvp[NSPLIT*B_*H_*DK_*DK_];
__device__ float g_ksump[NSPLIT*B_*H_*DK_];
__device__ float g_kv[B_*H_*DK_*DK_];
__device__ float g_ksum[B_*H_*DK_];

// ---------------- helpers -----------------------------------------------------
__device__ __forceinline__ uint32_t smem_u32(const void* p) {
    uint32_t a;
    asm("{ .reg .u64 t; cvta.to.shared.u64 t, %1; cvt.u32.u64 %0, t; }" : "=r"(a) : "l"(p));
    return a;
}

#define LDSM_X4(r, addr) \
    asm volatile("ldmatrix.sync.aligned.m8n8.x4.shared.b16 {%0,%1,%2,%3}, [%4];" \
        : "=r"((r)[0]), "=r"((r)[1]), "=r"((r)[2]), "=r"((r)[3]) : "r"(addr))

#define LDSM_X2(r, addr) \
    asm volatile("ldmatrix.sync.aligned.m8n8.x2.shared.b16 {%0,%1}, [%2];" \
        : "=r"((r)[0]), "=r"((r)[1]) : "r"(addr))

#define MMA_F16(d, a, b) \
    asm volatile("mma.sync.aligned.m16n8k16.row.col.f32.f16.f16.f32 " \
        "{%0,%1,%2,%3},{%4,%5,%6,%7},{%8,%9},{%0,%1,%2,%3};" \
        : "+f"((d)[0]), "+f"((d)[1]), "+f"((d)[2]), "+f"((d)[3]) \
        : "r"((a)[0]), "r"((a)[1]), "r"((a)[2]), "r"((a)[3]), \
          "r"((b)[0]), "r"((b)[1]))

#define CP_ASYNC16(dst_u32, src_gptr) \
    asm volatile("cp.async.cg.shared.global [%0], [%1], 16;" \
        :: "r"(dst_u32), "l"(src_gptr))

#define CP_COMMIT() asm volatile("cp.async.commit_group;")
#define CP_WAIT1()  asm volatile("cp.async.wait_group 1;")

template<int ACT>
__device__ __forceinline__ float actf(float v) {
    if (ACT == 1) return v > 0.f ? v + 1.f : __expf(v);   // elu(x)+1
    return v;
}

// ---------------- pre-conversion kernels --------------------------------------
__global__ __launch_bounds__(256) void cvt_x_kernel(const float* __restrict__ x) {
    int i = blockIdx.x * 256 + threadIdx.x;          // float4 index
    float4 f = ((const float4*)x)[i];
    __half2 h0 = __floats2half2_rn(f.x, f.y);
    __half2 h1 = __floats2half2_rn(f.z, f.w);
    uint2 hi;
    hi.x = *(uint32_t*)&h0; hi.y = *(uint32_t*)&h1;
    ((uint2*)g_xhi)[i] = hi;
}

__global__ __launch_bounds__(256) void cvt_w_kernel(const float* __restrict__ W, int slot) {
    int i = blockIdx.x * 256 + threadIdx.x;          // float4 index
    float4 f = ((const float4*)W)[i];
    __half2 h0 = __floats2half2_rn(f.x, f.y);
    __half2 h1 = __floats2half2_rn(f.z, f.w);
    uint2 hi;
    hi.x = *(uint32_t*)&h0; hi.y = *(uint32_t*)&h1;
    ((uint2*)(g_whi + (size_t)slot * D_ * D_))[i] = hi;
}

// ---------------- HMMA GEMM: C = act(A @ W^T + bias), pure fp16 inputs -------
// cp.async 3-stage pipeline, 2 CTAs/SM. CTA tile 128x128, 8 warps, BK=32.
#define BKF 32
#define NCHUNK (K_/BKF)      // 32
#define PADB 80              // bytes per smem row (40 fp16) - conflict-free ldmatrix
#define TILE_B (128*PADB)    // 10240
#define STAGE_B (2*TILE_B)   // A, W
#define NSTAGE 3
#define GSMEM (NSTAGE*STAGE_B)   // 61440

// one stage: 2 tiles x 128 rows x 64B; 4 cp.async16 per thread.
__device__ __forceinline__ void issue_stage(const __half* __restrict__ A,
                                            const __half* __restrict__ W,
                                            int m0, int n0, int kc,
                                            uint32_t stage_u, int tid, bool live) {
    if (live) {
        const int kb = kc * BKF;
#pragma unroll
        for (int j = 0; j < 4; j++) {
            int seg  = tid + j * 256;          // 0..1023
            int rem  = seg & 511;
            int row  = rem >> 2;
            int s4   = rem & 3;
            const __half* src;
            uint32_t dst;
            if (j < 2) {
                src = A + (size_t)(m0 + row) * K_ + kb + s4 * 8;
                dst = stage_u + row * PADB + s4 * 16;
            } else {
                src = W + (size_t)(n0 + row) * K_ + kb + s4 * 8;
                dst = stage_u + TILE_B + row * PADB + s4 * 16;
            }
            CP_ASYNC16(dst, src);
        }
    }
    CP_COMMIT();
}

template<int ACT>
__device__ __forceinline__ void gemm_body(const __half* __restrict__ A,
                                          const __half* __restrict__ W,
                                          const float* __restrict__ bias,
                                          float* __restrict__ C) {
    extern __shared__ char smem[];
    const int tid    = threadIdx.x;
    const int lane   = tid & 31;
    const int wid    = tid >> 5;
    const int warp_m = wid >> 2;       // 0..1
    const int warp_n = wid & 3;        // 0..3
    const int m0     = blockIdx.y * 128;
    const int n0     = blockIdx.x * 128;
    const uint32_t sbase = smem_u32(smem);

    float acc[4][4][4];
#pragma unroll
    for (int mi = 0; mi < 4; mi++)
#pragma unroll
        for (int ni = 0; ni < 4; ni++)
#pragma unroll
            for (int t = 0; t < 4; t++) acc[mi][ni][t] = 0.f;

    issue_stage(A, W, m0, n0, 0, sbase,           tid, true);
    issue_stage(A, W, m0, n0, 1, sbase + STAGE_B, tid, true);

    int stage = 0;
    for (int kc = 0; kc < NCHUNK; kc++) {
        CP_WAIT1();
        __syncthreads();

        int nst = stage + 2; if (nst >= NSTAGE) nst -= NSTAGE;
        issue_stage(A, W, m0, n0, kc + 2, sbase + nst * STAGE_B,
                    tid, kc + 2 < NCHUNK);

        const uint32_t base = sbase + stage * STAGE_B;

#pragma unroll
        for (int ks = 0; ks < 2; ks++) {
            uint32_t bhi[4][2];
            const int l2   = lane & 15;
            const int bk   = ks * 32 + ((l2 >> 3) & 1) * 16;
            const int brow = warp_n * 32 + (l2 & 7);
#pragma unroll
            for (int ni = 0; ni < 4; ni++) {
                uint32_t addr = base + TILE_B + (uint32_t)(brow + ni * 8) * PADB + bk;
                LDSM_X2(bhi[ni], addr);
            }
            const int arow = warp_m * 64 + (lane & 15);
            const int ak   = ks * 32 + (lane >> 4) * 16;
            uint32_t ah[4][4];
#pragma unroll
            for (int mi = 0; mi < 4; mi++) {
                uint32_t aaddr = base + (uint32_t)(arow + mi * 16) * PADB + ak;
                LDSM_X4(ah[mi], aaddr);
            }
#pragma unroll
            for (int mi = 0; mi < 4; mi++)
#pragma unroll
                for (int ni = 0; ni < 4; ni++)
                    MMA_F16(acc[mi][ni], ah[mi], bhi[ni]);
        }

        if (++stage >= NSTAGE) stage = 0;
    }

    // ---- epilogue: bias + activation ----
#pragma unroll
    for (int mi = 0; mi < 4; mi++) {
        int r0 = m0 + warp_m * 64 + mi * 16 + (lane >> 2);
#pragma unroll
        for (int ni = 0; ni < 4; ni++) {
            int c = n0 + warp_n * 32 + ni * 8 + (lane & 3) * 2;
            float b0v = bias[c], b1v = bias[c + 1];
            float2 o0, o1;
            o0.x = actf<ACT>(acc[mi][ni][0] + b0v);
            o0.y = actf<ACT>(acc[mi][ni][1] + b1v);
            o1.x = actf<ACT>(acc[mi][ni][2] + b0v);
            o1.y = actf<ACT>(acc[mi][ni][3] + b1v);
            *(float2*)&C[(size_t)r0 * N_ + c]       = o0;
            *(float2*)&C[(size_t)(r0 + 8) * N_ + c] = o1;
        }
    }
}

__global__ void __launch_bounds__(256, 2)
gemm_q_tc(const float* __restrict__ b) {
    gemm_body<1>(g_xhi, g_whi, b, g_q);
}
__global__ void __launch_bounds__(256, 2)
gemm_k_tc(const float* __restrict__ b) {
    gemm_body<1>(g_xhi, g_whi + (size_t)D_*D_, b, g_k);
}
__global__ void __launch_bounds__(256, 2)
gemm_v_tc(const float* __restrict__ b) {
    gemm_body<0>(g_xhi, g_whi + (size_t)2*D_*D_, b, g_v);
}
__global__ void __launch_bounds__(256, 2)
gemm_o_tc(const float* __restrict__ b, float* __restrict__ out) {
    gemm_body<0>(g_ahi, g_whi + (size_t)3*D_*D_, b, out);
}

// ---------------- kv summary (split partials, deterministic) ------------------
__global__ __launch_bounds__(256) void kv_kernel() {
    __shared__ float ks[16 * 64];
    __shared__ float vs[16 * 64];
    const int tid   = threadIdx.x;
    const int bh    = blockIdx.x;
    const int split = blockIdx.y;
    const int b     = bh >> 4;
    const int h     = bh & 15;
    const int tbase = split * TSPLIT;

    const float* kb = g_k + ((size_t)(b * T_ + tbase) * D_) + h * DK_;
    const float* vb = g_v + ((size_t)(b * T_ + tbase) * D_) + h * DK_;

    const int r0 = (tid >> 4) * 4;
    const int c0 = (tid & 15) * 4;
    const int lrow = tid >> 4;
    const int lc4  = (tid & 15) * 4;

    float acc[4][4];
#pragma unroll
    for (int i = 0; i < 4; i++)
#pragma unroll
        for (int j = 0; j < 4; j++) acc[i][j] = 0.f;
    float s = 0.f;

    for (int g = 0; g < TSPLIT / 16; g++) {
        __syncthreads();
        {
            float4 kk = *(const float4*)(kb + (size_t)(g * 16 + lrow) * D_ + lc4);
            float4 vv = *(const float4*)(vb + (size_t)(g * 16 + lrow) * D_ + lc4);
            *(float4*)&ks[lrow * 64 + lc4] = kk;
            *(float4*)&vs[lrow * 64 + lc4] = vv;
        }
        __syncthreads();
#pragma unroll
        for (int tt = 0; tt < 16; tt++) {
            float4 k4 = *(float4*)&ks[tt * 64 + r0];
            float4 v4 = *(float4*)&vs[tt * 64 + c0];
            float kr[4] = {k4.x, k4.y, k4.z, k4.w};
            float vc[4] = {v4.x, v4.y, v4.z, v4.w};
#pragma unroll
            for (int i = 0; i < 4; i++)
#pragma unroll
                for (int j = 0; j < 4; j++)
                    acc[i][j] = fmaf(kr[i], vc[j], acc[i][j]);
        }
        if (tid < 64) {
#pragma unroll
            for (int tt = 0; tt < 16; tt++) s += ks[tt * 64 + tid];
        }
    }

    float* dst = g_kvp + (size_t)split * (B_*H_*DK_*DK_) + (size_t)bh * (DK_*DK_);
#pragma unroll
    for (int i = 0; i < 4; i++)
#pragma unroll
        for (int j = 0; j < 4; j++)
            dst[(r0 + i) * DK_ + c0 + j] = acc[i][j];
    if (tid < 64)
        g_ksump[(size_t)split * (B_*H_*DK_) + bh * DK_ + tid] = s;
}

__global__ __launch_bounds__(256) void kv_reduce_kernel() {
    int i = blockIdx.x * 256 + threadIdx.x;
    if (i < B_*H_*DK_*DK_) {
        float s = 0.f;
#pragma unroll
        for (int sp = 0; sp < NSPLIT; sp++) s += g_kvp[(size_t)sp * (B_*H_*DK_*DK_) + i];
        g_kv[i] = s;
    }
    if (i < B_*H_*DK_) {
        float s = 0.f;
#pragma unroll
        for (int sp = 0; sp < NSPLIT; sp++) s += g_ksump[(size_t)sp * (B_*H_*DK_) + i];
        g_ksum[i] = s;
    }
}

// ---------------- attention apply (emits fp16 for O-GEMM) ---------------------
__global__ __launch_bounds__(256) void attn_kernel() {
    __shared__ float qs[64 * 64];
    __shared__ float kvs[64 * 64];
    __shared__ float ksums[64];
    __shared__ float zs[64];

    const int tid = threadIdx.x;
    const int bh  = blockIdx.x;
    const int b   = bh >> 4;
    const int h   = bh & 15;
    const int t0  = blockIdx.y * 64;

    const float* qbase = g_q + ((size_t)(b * T_ + t0) * D_) + h * DK_;

    for (int i = tid; i < 4096; i += 256)
        kvs[i] = g_kv[(size_t)bh * 4096 + i];
    if (tid < 64)
        ksums[tid] = g_ksum[bh * DK_ + tid] + EPS;

    for (int i = tid; i < 1024; i += 256) {
        int t  = i >> 4;
        int c4 = (i & 15) * 4;
        float4 v = *(const float4*)(qbase + (size_t)t * D_ + c4);
        qs[(c4+0)*64 + t] = v.x;
        qs[(c4+1)*64 + t] = v.y;
        qs[(c4+2)*64 + t] = v.z;
        qs[(c4+3)*64 + t] = v.w;
    }
    __syncthreads();

    if (tid < 64) {
        float zn = 0.f;
#pragma unroll
        for (int d = 0; d < 64; d++) zn = fmaf(qs[d*64 + tid], ksums[d], zn);
        zs[tid] = 1.f / (zn + EPS);
    }
    __syncthreads();

    const int tx = tid & 15;
    const int ty = tid >> 4;
    float acc[4][4];
#pragma unroll
    for (int i = 0; i < 4; i++)
#pragma unroll
        for (int j = 0; j < 4; j++) acc[i][j] = 0.f;

#pragma unroll
    for (int d = 0; d < 64; d++) {
        float4 a4 = *(float4*)&qs[d*64 + ty*4];
        float4 b4 = *(float4*)&kvs[d*64 + tx*4];
        float a[4] = {a4.x, a4.y, a4.z, a4.w};
        float bb[4] = {b4.x, b4.y, b4.z, b4.w};
#pragma unroll
        for (int i = 0; i < 4; i++)
#pragma unroll
            for (int j = 0; j < 4; j++)
                acc[i][j] = fmaf(a[i], bb[j], acc[i][j]);
    }

#pragma unroll
    for (int i = 0; i < 4; i++) {
        int t = ty * 4 + i;
        float z = zs[t];
        __half2 h0 = __floats2half2_rn(acc[i][0]*z, acc[i][1]*z);
        __half2 h1 = __floats2half2_rn(acc[i][2]*z, acc[i][3]*z);
        size_t off = (size_t)(b * T_ + t0 + t) * D_ + h * DK_ + tx * 4;
        uint2 hi; hi.x = *(uint32_t*)&h0; hi.y = *(uint32_t*)&h1;
        *(uint2*)(g_ahi + off) = hi;
    }
}

// ---------------- launch ----------------------------------------------------
extern "C" void kernel_launch(void* const* d_in, const int* in_sizes, int n_in,
                              void* d_out, int out_size) {
    const float* x  = (const float*)d_in[0];
    const float* Wq = (const float*)d_in[1];
    const float* bq = (const float*)d_in[2];
    const float* Wk = (const float*)d_in[3];
    const float* bk = (const float*)d_in[4];
    const float* Wv = (const float*)d_in[5];
    const float* bv = (const float*)d_in[6];
    const float* Wo = (const float*)d_in[7];
    const float* bo = (const float*)d_in[8];
    float* out = (float*)d_out;

    static bool attr_set = false;
    if (!attr_set) {
        cudaFuncSetAttribute(gemm_q_tc, cudaFuncAttributeMaxDynamicSharedMemorySize, GSMEM);
        cudaFuncSetAttribute(gemm_k_tc, cudaFuncAttributeMaxDynamicSharedMemorySize, GSMEM);
        cudaFuncSetAttribute(gemm_v_tc, cudaFuncAttributeMaxDynamicSharedMemorySize, GSMEM);
        cudaFuncSetAttribute(gemm_o_tc, cudaFuncAttributeMaxDynamicSharedMemorySize, GSMEM);
        attr_set = true;
    }

    cvt_x_kernel<<<M_*D_/4/256, 256>>>(x);
    cvt_w_kernel<<<D_*D_/4/256, 256>>>(Wq, 0);
    cvt_w_kernel<<<D_*D_/4/256, 256>>>(Wk, 1);
    cvt_w_kernel<<<D_*D_/4/256, 256>>>(Wv, 2);
    cvt_w_kernel<<<D_*D_/4/256, 256>>>(Wo, 3);

    dim3 gg(N_ / 128, M_ / 128);   // (8, 128)
    gemm_q_tc<<<gg, 256, GSMEM>>>(bq);
    gemm_k_tc<<<gg, 256, GSMEM>>>(bk);
    gemm_v_tc<<<gg, 256, GSMEM>>>(bv);
    kv_kernel<<<dim3(B_*H_, NSPLIT), 256>>>();
    kv_reduce_kernel<<<(B_*H_*DK_*DK_ + 255) / 256, 256>>>();
    attn_kernel<<<dim3(B_*H_, T_ / 64), 256>>>();
    gemm_o_tc<<<gg, 256, GSMEM>>>(bo, out);
}